// round 5
// baseline (speedup 1.0000x reference)
#include <cuda_runtime.h>
#include <math.h>
#include <stdint.h>

// ---------------------------------------------------------------------------
// Problem constants
// ---------------------------------------------------------------------------
#define TT     4096
#define HH     4096
#define NHEADS 32
#define NKV    8
#define HD     128
#define BATCH  4
#define QLEN   1024
#define HIST   1024
#define KVLEN  2048
#define WINDOW 1024
#define DKV    (NKV*HD)
#define SCALE  0.08838834764831845f

// ---------------------------------------------------------------------------
// Scratch
// ---------------------------------------------------------------------------
__device__ float g_q[(size_t)TT * HH];
__device__ float g_k[(size_t)TT * DKV];
__device__ float g_v[(size_t)TT * DKV];
__device__ float g_o[(size_t)TT * HH];

// ---------------------------------------------------------------------------
// Packed f32x2 helpers (sm_100+ base ISA -> SASS FFMA2)
// ---------------------------------------------------------------------------
typedef unsigned long long u64t;

__device__ __forceinline__ u64t dup2(float a) {
    u64t d; uint32_t r = __float_as_uint(a);
    asm("mov.b64 %0, {%1, %1};" : "=l"(d) : "r"(r));
    return d;
}
__device__ __forceinline__ u64t pack2(float lo, float hi) {
    u64t d; asm("mov.b64 %0, {%1, %2};" : "=l"(d) : "r"(__float_as_uint(lo)), "r"(__float_as_uint(hi)));
    return d;
}
__device__ __forceinline__ void ffma2(u64t& d, u64t a, u64t b) {
    asm("fma.rn.f32x2 %0, %1, %2, %0;" : "+l"(d) : "l"(a), "l"(b));
}
__device__ __forceinline__ u64t fmul2(u64t a, u64t b) {
    u64t d; asm("mul.rn.f32x2 %0, %1, %2;" : "=l"(d) : "l"(a), "l"(b));
    return d;
}

// ---------------------------------------------------------------------------
// SGEMM with packed FFMA2: C[M,N] = A[M,K] @ B[K,N]
// 128x128 block tile, 8x8 per thread (acc = 8 rows x 4 f32x2), BK=8, 256 thr.
// ---------------------------------------------------------------------------
__global__ __launch_bounds__(256) void sgemm2_kernel(
    int M, int N, int K,
    const float* __restrict__ A, const float* __restrict__ B, float* __restrict__ C)
{
    constexpr int BM = 128, BN = 128, BK = 8;
    __shared__ float As[BK * BM];
    __shared__ float Bs[BK * BN];

    const int tid = threadIdx.x;
    const int bx = blockIdx.x, by = blockIdx.y;

    const int aRow = tid >> 1;
    const int aCol = (tid & 1) * 4;
    const int bRow = tid >> 5;
    const int bCol = (tid & 31) * 4;
    const int tRow = (tid >> 4) * 8;
    const int tCol = (tid & 15) * 8;

    const float* Ab = A + (size_t)by * BM * K;
    const float* Bb = B + (size_t)bx * BN;

    u64t acc[8][4];
#pragma unroll
    for (int i = 0; i < 8; i++)
#pragma unroll
        for (int j = 0; j < 4; j++) acc[i][j] = 0ull;

    for (int k0 = 0; k0 < K; k0 += BK) {
        float4 a4 = *(const float4*)(Ab + (size_t)aRow * K + k0 + aCol);
        As[(aCol + 0) * BM + aRow] = a4.x;
        As[(aCol + 1) * BM + aRow] = a4.y;
        As[(aCol + 2) * BM + aRow] = a4.z;
        As[(aCol + 3) * BM + aRow] = a4.w;
        *(float4*)(Bs + bRow * BN + bCol) =
            *(const float4*)(Bb + (size_t)(k0 + bRow) * N + bCol);
        __syncthreads();

#pragma unroll
        for (int kk = 0; kk < BK; ++kk) {
            // A: 8 consecutive rows -> 4 float2 loads, duplicate each scalar
            float2 a01 = *(const float2*)&As[kk * BM + tRow];
            float2 a23 = *(const float2*)&As[kk * BM + tRow + 2];
            float2 a45 = *(const float2*)&As[kk * BM + tRow + 4];
            float2 a67 = *(const float2*)&As[kk * BM + tRow + 6];
            u64t ad[8];
            ad[0] = dup2(a01.x); ad[1] = dup2(a01.y);
            ad[2] = dup2(a23.x); ad[3] = dup2(a23.y);
            ad[4] = dup2(a45.x); ad[5] = dup2(a45.y);
            ad[6] = dup2(a67.x); ad[7] = dup2(a67.y);
            // B: 8 consecutive cols -> 4 packed u64 loads (adjacent pairs)
            u64t rb[4];
            rb[0] = *(const u64t*)&Bs[kk * BN + tCol];
            rb[1] = *(const u64t*)&Bs[kk * BN + tCol + 2];
            rb[2] = *(const u64t*)&Bs[kk * BN + tCol + 4];
            rb[3] = *(const u64t*)&Bs[kk * BN + tCol + 6];
#pragma unroll
            for (int i = 0; i < 8; i++)
#pragma unroll
                for (int j = 0; j < 4; j++)
                    ffma2(acc[i][j], ad[i], rb[j]);
        }
        __syncthreads();
    }

    float* Cb = C + (size_t)(by * BM + tRow) * N + bx * BN + tCol;
#pragma unroll
    for (int i = 0; i < 8; i++) {
        u64t* dst = (u64t*)(Cb + (size_t)i * N);
#pragma unroll
        for (int j = 0; j < 4; j++) dst[j] = acc[i][j];
    }
}

// ---------------------------------------------------------------------------
// RoPE (unchanged)
// ---------------------------------------------------------------------------
__global__ void rope_kernel(float* __restrict__ x, int heads)
{
    int idx = blockIdx.x * blockDim.x + threadIdx.x;
    int total = TT * heads * 64;
    if (idx >= total) return;
    int j  = idx & 63;
    int th = idx >> 6;
    int h  = th % heads;
    int t  = th / heads;
    int pos = HIST + (t & (QLEN - 1));

    float e = (float)(2 * j) * (1.0f / 128.0f);
    float freq = powf(1.0e6f, -e);
    float ang = (float)pos * freq;
    float s, c;
    sincosf(ang, &s, &c);

    size_t base = (size_t)t * heads * HD + (size_t)h * HD + j;
    float x0 = x[base];
    float x1 = x[base + 64];
    x[base]      = x0 * c - x1 * s;
    x[base + 64] = x1 * c + x0 * s;
}

// ---------------------------------------------------------------------------
// Flash-style attention; PV inner product converted to packed FFMA2.
// ---------------------------------------------------------------------------
#define ATTN_SMEM_FLOATS (64*129 + 64*129 + 64*128 + 64*65 + 64)
#define ATTN_SMEM_BYTES  (ATTN_SMEM_FLOATS * 4)

__global__ __launch_bounds__(256) void attn_kernel(
    const float* __restrict__ kcache, const float* __restrict__ vcache)
{
    const int i0  = blockIdx.x * 64;
    const int h   = blockIdx.y;
    const int b   = blockIdx.z;
    const int kvh = h >> 2;
    const int tid = threadIdx.x;

    extern __shared__ float sm[];
    float* sQ = sm;
    float* sK = sQ + 64 * 129;
    float* sV = sK + 64 * 129;
    float* sS = sV + 64 * 128;
    float* sA = sS + 64 * 65;

#pragma unroll
    for (int it = 0; it < 8; ++it) {
        int idx = it * 256 + tid;
        int r = idx >> 5;
        int d4 = (idx & 31) * 4;
        float4 v = *(const float4*)&g_q[(size_t)(b * QLEN + i0 + r) * HH + h * HD + d4];
        float* dst = &sQ[r * 129 + d4];
        dst[0] = v.x; dst[1] = v.y; dst[2] = v.z; dst[3] = v.w;
    }

    const int sy = tid >> 4, sx = tid & 15;
    const int row = tid >> 2, l4 = tid & 3;

    float m = -3.0e38f, l = 0.f;
    u64t o[4][4];   // 4 rows x 8 cols as 4 packed f32x2
#pragma unroll
    for (int r = 0; r < 4; r++)
#pragma unroll
        for (int c = 0; c < 4; c++) o[r][c] = 0ull;

    const int qpos0 = HIST + i0;

    for (int t = 0; t < 17; ++t) {
        const int p0 = i0 + t * 64;
        __syncthreads();

#pragma unroll
        for (int it = 0; it < 8; ++it) {
            int idx = it * 256 + tid;
            int r = idx >> 5;
            int d4 = (idx & 31) * 4;
            int p = p0 + r;
            const float *src_k, *src_v;
            if (p < HIST) {
                size_t base = ((size_t)(b * KVLEN + p) * NKV + kvh) * HD + d4;
                src_k = kcache + base;
                src_v = vcache + base;
            } else {
                size_t base = (size_t)(b * QLEN + (p - HIST)) * DKV + kvh * HD + d4;
                src_k = g_k + base;
                src_v = g_v + base;
            }
            float4 kv = *(const float4*)src_k;
            float* kd = &sK[r * 129 + d4];
            kd[0] = kv.x; kd[1] = kv.y; kd[2] = kv.z; kd[3] = kv.w;
            *(float4*)&sV[r * 128 + d4] = *(const float4*)src_v;
        }
        __syncthreads();

        // ---- scores: S = Q @ K^T, 4x4 per thread (packed over column pairs) ----
        u64t accp[4][2];
#pragma unroll
        for (int r = 0; r < 4; r++) { accp[r][0] = 0ull; accp[r][1] = 0ull; }

        for (int kk = 0; kk < 128; ++kk) {
            u64t ra[4];
#pragma unroll
            for (int r = 0; r < 4; r++) ra[r] = dup2(sQ[(sy * 4 + r) * 129 + kk]);
            u64t rb0 = pack2(sK[(sx * 4 + 0) * 129 + kk], sK[(sx * 4 + 1) * 129 + kk]);
            u64t rb1 = pack2(sK[(sx * 4 + 2) * 129 + kk], sK[(sx * 4 + 3) * 129 + kk]);
#pragma unroll
            for (int r = 0; r < 4; r++) {
                ffma2(accp[r][0], ra[r], rb0);
                ffma2(accp[r][1], ra[r], rb1);
            }
        }

        // ---- mask + store S ----
#pragma unroll
        for (int r = 0; r < 4; r++) {
            int qp = qpos0 + sy * 4 + r;
            float av[4];
            uint32_t lo, hi;
            asm("mov.b64 {%0,%1}, %2;" : "=r"(lo), "=r"(hi) : "l"(accp[r][0]));
            av[0] = __uint_as_float(lo); av[1] = __uint_as_float(hi);
            asm("mov.b64 {%0,%1}, %2;" : "=r"(lo), "=r"(hi) : "l"(accp[r][1]));
            av[2] = __uint_as_float(lo); av[3] = __uint_as_float(hi);
#pragma unroll
            for (int c = 0; c < 4; c++) {
                int kp = p0 + sx * 4 + c;
                float s = av[c] * SCALE;
                bool valid = (kp <= qp) && ((qp - kp) < WINDOW);
                sS[(sy * 4 + r) * 65 + sx * 4 + c] = valid ? s : -3.0e38f;
            }
        }
        __syncthreads();

        // ---- online softmax ----
        float tm = -3.0e38f;
#pragma unroll
        for (int j = 0; j < 16; j++) tm = fmaxf(tm, sS[row * 65 + l4 * 16 + j]);
        tm = fmaxf(tm, __shfl_xor_sync(0xffffffffu, tm, 1));
        tm = fmaxf(tm, __shfl_xor_sync(0xffffffffu, tm, 2));
        float mnew = fmaxf(m, tm);
        float alpha = __expf(m - mnew);
        float psum = 0.f;
#pragma unroll
        for (int j = 0; j < 16; j++) {
            float p = __expf(sS[row * 65 + l4 * 16 + j] - mnew);
            sS[row * 65 + l4 * 16 + j] = p;
            psum += p;
        }
        psum += __shfl_xor_sync(0xffffffffu, psum, 1);
        psum += __shfl_xor_sync(0xffffffffu, psum, 2);
        l = l * alpha + psum;
        m = mnew;
        if (l4 == 0) sA[row] = alpha;
        __syncthreads();

        // ---- O = O*alpha + P @ V (packed f32x2 over V column pairs) ----
#pragma unroll
        for (int r = 0; r < 4; r++) {
            u64t a2 = dup2(sA[sy * 4 + r]);
#pragma unroll
            for (int c = 0; c < 4; c++) o[r][c] = fmul2(o[r][c], a2);
        }
        for (int j = 0; j < 64; ++j) {
            u64t p[4];
#pragma unroll
            for (int r = 0; r < 4; r++) p[r] = dup2(sS[(sy * 4 + r) * 65 + j]);
            const u64t* vrow = (const u64t*)&sV[j * 128 + sx * 8];
            u64t v0 = vrow[0], v1 = vrow[1], v2 = vrow[2], v3 = vrow[3];
#pragma unroll
            for (int r = 0; r < 4; r++) {
                ffma2(o[r][0], p[r], v0);
                ffma2(o[r][1], p[r], v1);
                ffma2(o[r][2], p[r], v2);
                ffma2(o[r][3], p[r], v3);
            }
        }
    }

    // ---- finalize ----
    __syncthreads();
    if (l4 == 0) sA[row] = 1.0f / l;
    __syncthreads();
#pragma unroll
    for (int r = 0; r < 4; r++) {
        u64t inv2 = dup2(sA[sy * 4 + r]);
        u64t* dst = (u64t*)&g_o[(size_t)(b * QLEN + i0 + sy * 4 + r) * HH + h * HD + sx * 8];
#pragma unroll
        for (int c = 0; c < 4; c++) dst[c] = fmul2(o[r][c], inv2);
    }
}

// ---------------------------------------------------------------------------
// Launch
// ---------------------------------------------------------------------------
extern "C" void kernel_launch(void* const* d_in, const int* in_sizes, int n_in,
                              void* d_out, int out_size)
{
    const float* hs = (const float*)d_in[0];
    const float* wq = (const float*)d_in[1];
    const float* wk = (const float*)d_in[2];
    const float* wv = (const float*)d_in[3];
    const float* wo = (const float*)d_in[4];
    const float* kc = (const float*)d_in[5];
    const float* vc = (const float*)d_in[6];

    float *qb, *kb, *vb, *ob;
    cudaGetSymbolAddress((void**)&qb, g_q);
    cudaGetSymbolAddress((void**)&kb, g_k);
    cudaGetSymbolAddress((void**)&vb, g_v);
    cudaGetSymbolAddress((void**)&ob, g_o);

    cudaFuncSetAttribute(attn_kernel, cudaFuncAttributeMaxDynamicSharedMemorySize,
                         ATTN_SMEM_BYTES);

    dim3 gq(HH / 128, TT / 128);     // 32 x 32
    dim3 gkv(DKV / 128, TT / 128);   // 8 x 32

    sgemm2_kernel<<<gq,  256>>>(TT, HH,  HH, hs, wq, qb);
    sgemm2_kernel<<<gkv, 256>>>(TT, DKV, HH, hs, wk, kb);
    sgemm2_kernel<<<gkv, 256>>>(TT, DKV, HH, hs, wv, vb);

    {
        int totq = TT * NHEADS * 64;
        rope_kernel<<<(totq + 255) / 256, 256>>>(qb, NHEADS);
        int totk = TT * NKV * 64;
        rope_kernel<<<(totk + 255) / 256, 256>>>(kb, NKV);
    }

    dim3 ga(QLEN / 64, NHEADS, BATCH);
    attn_kernel<<<ga, 256, ATTN_SMEM_BYTES>>>(kc, vc);

    sgemm2_kernel<<<gq, 256>>>(TT, HH, HH, ob, wo, (float*)d_out);
}

// round 10
// speedup vs baseline: 1.8401x; 1.8401x over previous
#include <cuda_runtime.h>
#include <cuda_fp16.h>
#include <math.h>
#include <stdint.h>

// ---------------------------------------------------------------------------
// Problem constants
// ---------------------------------------------------------------------------
#define TT     4096
#define HH     4096
#define NHEADS 32
#define NKV    8
#define HD     128
#define BATCH  4
#define QLEN   1024
#define HIST   1024
#define KVLEN  2048
#define WINDOW 1024
#define DKV    (NKV*HD)
#define SCALE  0.08838834764831845f

// ---------------------------------------------------------------------------
// Scratch
// ---------------------------------------------------------------------------
__device__ float g_q[(size_t)TT * HH];
__device__ float g_k[(size_t)TT * DKV];
__device__ float g_v[(size_t)TT * DKV];
__device__ float g_o[(size_t)TT * HH];

// ---------------------------------------------------------------------------
// fp16x3 tensor-core GEMM: C[M,N] = A[M,K] @ B[K,N]
// CTA tile 128x128x32, 256 threads = 8 warps (4M x 2N), warp tile 32x64.
// mma.sync.aligned.m16n8k16.row.col.f32.f16.f16.f32, error-compensated:
//   a = ah + al (ah = fp16(a), al = fp16(a-ah)); a*b ~= ah*bh + ah*bl + al*bh
// smem half-tiles stored as packed half2 (uint32), k-pair-major:
//   Ah/Al: [128 m][20 u32] (16 used + 4 pad)  -> frag LDS conflict-free
//   Bh/Bl: [128 n][20 u32]
// ---------------------------------------------------------------------------
#define USTR 20
#define STG_U 4224                    // float[32][132] staging for B transpose
#define OFF_AH (STG_U)
#define OFF_AL (OFF_AH + 128*USTR)
#define OFF_BH (OFF_AL + 128*USTR)
#define OFF_BL (OFF_BH + 128*USTR)
#define HG_SMEM_U32 (OFF_BL + 128*USTR)
#define HG_SMEM_BYTES (HG_SMEM_U32 * 4)

__device__ __forceinline__ void mma_f16(float* d, const uint32_t* a, uint32_t b0, uint32_t b1)
{
    asm volatile(
        "mma.sync.aligned.m16n8k16.row.col.f32.f16.f16.f32 "
        "{%0,%1,%2,%3}, {%4,%5,%6,%7}, {%8,%9}, {%0,%1,%2,%3};\n"
        : "+f"(d[0]), "+f"(d[1]), "+f"(d[2]), "+f"(d[3])
        : "r"(a[0]), "r"(a[1]), "r"(a[2]), "r"(a[3]), "r"(b0), "r"(b1));
}

__device__ __forceinline__ void split2(float x, float y, uint32_t& hi, uint32_t& lo)
{
    __half hx = __float2half_rn(x);
    __half hy = __float2half_rn(y);
    float lx = x - __half2float(hx);
    float ly = y - __half2float(hy);
    __half2 h = __halves2half2(hx, hy);
    __half2 l = __halves2half2(__float2half_rn(lx), __float2half_rn(ly));
    hi = *(uint32_t*)&h;
    lo = *(uint32_t*)&l;
}

__global__ __launch_bounds__(256) void hgemm3_kernel(
    int M, int N, int K,
    const float* __restrict__ A, const float* __restrict__ B, float* __restrict__ C)
{
    extern __shared__ uint32_t smu[];
    float*    stg = (float*)smu;          // [32][132]
    uint32_t* Ah  = smu + OFF_AH;
    uint32_t* Al  = smu + OFF_AL;
    uint32_t* Bh  = smu + OFF_BH;
    uint32_t* Bl  = smu + OFF_BL;

    const int tid  = threadIdx.x;
    const int lane = tid & 31;
    const int wid  = tid >> 5;
    const int wm   = (wid & 3) * 32;
    const int wn   = (wid >> 2) * 64;
    const int g    = lane >> 2;
    const int tg   = lane & 3;

    const float* Abase = A + (size_t)blockIdx.y * 128 * K;
    const float* Bbase = B + (size_t)blockIdx.x * 128;

    float acc[2][8][4];
#pragma unroll
    for (int mt = 0; mt < 2; mt++)
#pragma unroll
        for (int nt = 0; nt < 8; nt++)
#pragma unroll
            for (int i = 0; i < 4; i++) acc[mt][nt][i] = 0.f;

    // A load mapping: 128 rows x 32 k, float4 per thread x 4 iters
    const int am = tid >> 3;          // 0..31 (+32*it)
    const int ac = (tid & 7) * 4;     // k offset 0..28
    // B stage mapping
    const int bk0 = tid >> 5;         // 0..7 (+8*it)
    const int bn  = (tid & 31) * 4;
    // B transpose mapping: tid<128: n=tid, kp 0..7 ; tid>=128: n=tid-128, kp 8..15
    const int tn  = tid & 127;
    const int tkp = (tid >> 7) * 8;

    for (int k0 = 0; k0 < K; k0 += 32) {
        // ---- A tile: gmem [m][k] -> Ah/Al [m][k/2] packed ----
#pragma unroll
        for (int it = 0; it < 4; ++it) {
            int m = it * 32 + am;
            float4 v = *(const float4*)(Abase + (size_t)m * K + k0 + ac);
            uint32_t h0, l0, h1, l1;
            split2(v.x, v.y, h0, l0);
            split2(v.z, v.w, h1, l1);
            int o = m * USTR + (ac >> 1);
            Ah[o] = h0; Ah[o + 1] = h1;
            Al[o] = l0; Al[o + 1] = l1;
        }
        // ---- B stage: gmem [k][n] coalesced -> stg[k][n] (pad 132) ----
#pragma unroll
        for (int it = 0; it < 4; ++it) {
            int kk = it * 8 + bk0;
            *(float4*)&stg[kk * 132 + bn] =
                *(const float4*)(Bbase + (size_t)(k0 + kk) * N + bn);
        }
        __syncthreads();
        // ---- transpose-convert: stg[k][n] -> Bh/Bl [n][k/2] packed ----
#pragma unroll
        for (int j = 0; j < 8; ++j) {
            int kp = tkp + j;
            float x = stg[(2 * kp) * 132 + tn];
            float y = stg[(2 * kp + 1) * 132 + tn];
            uint32_t h, l;
            split2(x, y, h, l);
            Bh[tn * USTR + kp] = h;
            Bl[tn * USTR + kp] = l;
        }
        __syncthreads();

        // ---- MMA: 2 k16-slices x (2 mt x 8 nt x 3 terms) ----
#pragma unroll
        for (int ks = 0; ks < 2; ++ks) {
            uint32_t ah[2][4], al[2][4];
#pragma unroll
            for (int mt = 0; mt < 2; mt++) {
                int r0 = (wm + mt * 16 + g) * USTR + ks * 8 + tg;
                int r8 = r0 + 8 * USTR;
                ah[mt][0] = Ah[r0];     ah[mt][1] = Ah[r8];
                ah[mt][2] = Ah[r0 + 4]; ah[mt][3] = Ah[r8 + 4];
                al[mt][0] = Al[r0];     al[mt][1] = Al[r8];
                al[mt][2] = Al[r0 + 4]; al[mt][3] = Al[r8 + 4];
            }
#pragma unroll
            for (int nt = 0; nt < 8; nt++) {
                int nb = (wn + nt * 8 + g) * USTR + ks * 8 + tg;
                uint32_t bh0 = Bh[nb], bh1 = Bh[nb + 4];
                uint32_t bl0 = Bl[nb], bl1 = Bl[nb + 4];
#pragma unroll
                for (int mt = 0; mt < 2; mt++) {
                    mma_f16(acc[mt][nt], ah[mt], bh0, bh1);
                    mma_f16(acc[mt][nt], ah[mt], bl0, bl1);
                    mma_f16(acc[mt][nt], al[mt], bh0, bh1);
                }
            }
        }
        __syncthreads();
    }

    // ---- epilogue: direct float2 stores ----
#pragma unroll
    for (int mt = 0; mt < 2; mt++) {
        int row = blockIdx.y * 128 + wm + mt * 16 + g;
#pragma unroll
        for (int nt = 0; nt < 8; nt++) {
            int col = blockIdx.x * 128 + wn + nt * 8 + tg * 2;
            *(float2*)(C + (size_t)row * N + col)       = make_float2(acc[mt][nt][0], acc[mt][nt][1]);
            *(float2*)(C + (size_t)(row + 8) * N + col) = make_float2(acc[mt][nt][2], acc[mt][nt][3]);
        }
    }
}

// ---------------------------------------------------------------------------
// RoPE (unchanged)
// ---------------------------------------------------------------------------
__global__ void rope_kernel(float* __restrict__ x, int heads)
{
    int idx = blockIdx.x * blockDim.x + threadIdx.x;
    int total = TT * heads * 64;
    if (idx >= total) return;
    int j  = idx & 63;
    int th = idx >> 6;
    int h  = th % heads;
    int t  = th / heads;
    int pos = HIST + (t & (QLEN - 1));

    float e = (float)(2 * j) * (1.0f / 128.0f);
    float freq = powf(1.0e6f, -e);
    float ang = (float)pos * freq;
    float s, c;
    sincosf(ang, &s, &c);

    size_t base = (size_t)t * heads * HD + (size_t)h * HD + j;
    float x0 = x[base];
    float x1 = x[base + 64];
    x[base]      = x0 * c - x1 * s;
    x[base + 64] = x1 * c + x0 * s;
}

// ---------------------------------------------------------------------------
// Flash-style attention (known-good scalar version)
// ---------------------------------------------------------------------------
#define ATTN_SMEM_FLOATS (64*129 + 64*129 + 64*128 + 64*65 + 64)
#define ATTN_SMEM_BYTES  (ATTN_SMEM_FLOATS * 4)

__global__ __launch_bounds__(256) void attn_kernel(
    const float* __restrict__ kcache, const float* __restrict__ vcache)
{
    const int i0  = blockIdx.x * 64;
    const int h   = blockIdx.y;
    const int b   = blockIdx.z;
    const int kvh = h >> 2;
    const int tid = threadIdx.x;

    extern __shared__ float sm[];
    float* sQ = sm;
    float* sK = sQ + 64 * 129;
    float* sV = sK + 64 * 129;
    float* sS = sV + 64 * 128;
    float* sA = sS + 64 * 65;

#pragma unroll
    for (int it = 0; it < 8; ++it) {
        int idx = it * 256 + tid;
        int r = idx >> 5;
        int d4 = (idx & 31) * 4;
        float4 v = *(const float4*)&g_q[(size_t)(b * QLEN + i0 + r) * HH + h * HD + d4];
        float* dst = &sQ[r * 129 + d4];
        dst[0] = v.x; dst[1] = v.y; dst[2] = v.z; dst[3] = v.w;
    }

    const int sy = tid >> 4, sx = tid & 15;
    const int row = tid >> 2, l4 = tid & 3;

    float m = -3.0e38f, l = 0.f;
    float o[4][8];
#pragma unroll
    for (int r = 0; r < 4; r++)
#pragma unroll
        for (int c = 0; c < 8; c++) o[r][c] = 0.f;

    const int qpos0 = HIST + i0;

    for (int t = 0; t < 17; ++t) {
        const int p0 = i0 + t * 64;
        __syncthreads();

#pragma unroll
        for (int it = 0; it < 8; ++it) {
            int idx = it * 256 + tid;
            int r = idx >> 5;
            int d4 = (idx & 31) * 4;
            int p = p0 + r;
            const float *src_k, *src_v;
            if (p < HIST) {
                size_t base = ((size_t)(b * KVLEN + p) * NKV + kvh) * HD + d4;
                src_k = kcache + base;
                src_v = vcache + base;
            } else {
                size_t base = (size_t)(b * QLEN + (p - HIST)) * DKV + kvh * HD + d4;
                src_k = g_k + base;
                src_v = g_v + base;
            }
            float4 kv = *(const float4*)src_k;
            float* kd = &sK[r * 129 + d4];
            kd[0] = kv.x; kd[1] = kv.y; kd[2] = kv.z; kd[3] = kv.w;
            *(float4*)&sV[r * 128 + d4] = *(const float4*)src_v;
        }
        __syncthreads();

        float acc[4][4];
#pragma unroll
        for (int r = 0; r < 4; r++)
#pragma unroll
            for (int c = 0; c < 4; c++) acc[r][c] = 0.f;

        for (int kk = 0; kk < 128; ++kk) {
            float ra[4], rb[4];
#pragma unroll
            for (int r = 0; r < 4; r++) ra[r] = sQ[(sy * 4 + r) * 129 + kk];
#pragma unroll
            for (int c = 0; c < 4; c++) rb[c] = sK[(sx * 4 + c) * 129 + kk];
#pragma unroll
            for (int r = 0; r < 4; r++)
#pragma unroll
                for (int c = 0; c < 4; c++)
                    acc[r][c] = fmaf(ra[r], rb[c], acc[r][c]);
        }

#pragma unroll
        for (int r = 0; r < 4; r++) {
            int qp = qpos0 + sy * 4 + r;
#pragma unroll
            for (int c = 0; c < 4; c++) {
                int kp = p0 + sx * 4 + c;
                float s = acc[r][c] * SCALE;
                bool valid = (kp <= qp) && ((qp - kp) < WINDOW);
                sS[(sy * 4 + r) * 65 + sx * 4 + c] = valid ? s : -3.0e38f;
            }
        }
        __syncthreads();

        float tm = -3.0e38f;
#pragma unroll
        for (int j = 0; j < 16; j++) tm = fmaxf(tm, sS[row * 65 + l4 * 16 + j]);
        tm = fmaxf(tm, __shfl_xor_sync(0xffffffffu, tm, 1));
        tm = fmaxf(tm, __shfl_xor_sync(0xffffffffu, tm, 2));
        float mnew = fmaxf(m, tm);
        float alpha = __expf(m - mnew);
        float psum = 0.f;
#pragma unroll
        for (int j = 0; j < 16; j++) {
            float p = __expf(sS[row * 65 + l4 * 16 + j] - mnew);
            sS[row * 65 + l4 * 16 + j] = p;
            psum += p;
        }
        psum += __shfl_xor_sync(0xffffffffu, psum, 1);
        psum += __shfl_xor_sync(0xffffffffu, psum, 2);
        l = l * alpha + psum;
        m = mnew;
        if (l4 == 0) sA[row] = alpha;
        __syncthreads();

#pragma unroll
        for (int r = 0; r < 4; r++) {
            float a = sA[sy * 4 + r];
#pragma unroll
            for (int c = 0; c < 8; c++) o[r][c] *= a;
        }
        for (int j = 0; j < 64; ++j) {
            float p[4];
#pragma unroll
            for (int r = 0; r < 4; r++) p[r] = sS[(sy * 4 + r) * 65 + j];
            float4 v0 = *(float4*)&sV[j * 128 + sx * 8];
            float4 v1 = *(float4*)&sV[j * 128 + sx * 8 + 4];
            float vv[8] = {v0.x, v0.y, v0.z, v0.w, v1.x, v1.y, v1.z, v1.w};
#pragma unroll
            for (int r = 0; r < 4; r++)
#pragma unroll
                for (int c = 0; c < 8; c++)
                    o[r][c] = fmaf(p[r], vv[c], o[r][c]);
        }
    }

    __syncthreads();
    if (l4 == 0) sA[row] = 1.0f / l;
    __syncthreads();
#pragma unroll
    for (int r = 0; r < 4; r++) {
        float inv = sA[sy * 4 + r];
        float* dst = &g_o[(size_t)(b * QLEN + i0 + sy * 4 + r) * HH + h * HD + sx * 8];
#pragma unroll
        for (int c = 0; c < 8; c++) dst[c] = o[r][c] * inv;
    }
}

// ---------------------------------------------------------------------------
// Launch
// ---------------------------------------------------------------------------
extern "C" void kernel_launch(void* const* d_in, const int* in_sizes, int n_in,
                              void* d_out, int out_size)
{
    const float* hs = (const float*)d_in[0];
    const float* wq = (const float*)d_in[1];
    const float* wk = (const float*)d_in[2];
    const float* wv = (const float*)d_in[3];
    const float* wo = (const float*)d_in[4];
    const float* kc = (const float*)d_in[5];
    const float* vc = (const float*)d_in[6];

    float *qb, *kb, *vb, *ob;
    cudaGetSymbolAddress((void**)&qb, g_q);
    cudaGetSymbolAddress((void**)&kb, g_k);
    cudaGetSymbolAddress((void**)&vb, g_v);
    cudaGetSymbolAddress((void**)&ob, g_o);

    cudaFuncSetAttribute(attn_kernel, cudaFuncAttributeMaxDynamicSharedMemorySize,
                         ATTN_SMEM_BYTES);
    cudaFuncSetAttribute(hgemm3_kernel, cudaFuncAttributeMaxDynamicSharedMemorySize,
                         HG_SMEM_BYTES);

    dim3 gq(HH / 128, TT / 128);     // 32 x 32
    dim3 gkv(DKV / 128, TT / 128);   // 8 x 32

    hgemm3_kernel<<<gq,  256, HG_SMEM_BYTES>>>(TT, HH,  HH, hs, wq, qb);
    hgemm3_kernel<<<gkv, 256, HG_SMEM_BYTES>>>(TT, DKV, HH, hs, wk, kb);
    hgemm3_kernel<<<gkv, 256, HG_SMEM_BYTES>>>(TT, DKV, HH, hs, wv, vb);

    {
        int totq = TT * NHEADS * 64;
        rope_kernel<<<(totq + 255) / 256, 256>>>(qb, NHEADS);
        int totk = TT * NKV * 64;
        rope_kernel<<<(totk + 255) / 256, 256>>>(kb, NKV);
    }

    dim3 ga(QLEN / 64, NHEADS, BATCH);
    attn_kernel<<<ga, 256, ATTN_SMEM_BYTES>>>(kc, vc);

    hgemm3_kernel<<<gq, 256, HG_SMEM_BYTES>>>(TT, HH, HH, ob, wo, (float*)d_out);
}

// round 13
// speedup vs baseline: 2.2814x; 1.2398x over previous
#include <cuda_runtime.h>
#include <cuda_fp16.h>
#include <math.h>
#include <stdint.h>

// ---------------------------------------------------------------------------
// Problem constants
// ---------------------------------------------------------------------------
#define TT     4096
#define HH     4096
#define NHEADS 32
#define NKV    8
#define HD     128
#define BATCH  4
#define QLEN   1024
#define HIST   1024
#define KVLEN  2048
#define WINDOW 1024
#define DKV    (NKV*HD)
#define SCALE  0.08838834764831845f
#define NEGBIG (-3.0e38f)

// ---------------------------------------------------------------------------
// Scratch
// ---------------------------------------------------------------------------
__device__ float g_q[(size_t)TT * HH];
__device__ float g_k[(size_t)TT * DKV];
__device__ float g_v[(size_t)TT * DKV];
__device__ float g_o[(size_t)TT * HH];

// ---------------------------------------------------------------------------
// Shared fp16x3 helpers
// ---------------------------------------------------------------------------
__device__ __forceinline__ void mma_f16(float* d, const uint32_t* a, uint32_t b0, uint32_t b1)
{
    asm volatile(
        "mma.sync.aligned.m16n8k16.row.col.f32.f16.f16.f32 "
        "{%0,%1,%2,%3}, {%4,%5,%6,%7}, {%8,%9}, {%0,%1,%2,%3};\n"
        : "+f"(d[0]), "+f"(d[1]), "+f"(d[2]), "+f"(d[3])
        : "r"(a[0]), "r"(a[1]), "r"(a[2]), "r"(a[3]), "r"(b0), "r"(b1));
}

__device__ __forceinline__ void split2(float x, float y, uint32_t& hi, uint32_t& lo)
{
    __half hx = __float2half_rn(x);
    __half hy = __float2half_rn(y);
    float lx = x - __half2float(hx);
    float ly = y - __half2float(hy);
    __half2 h = __halves2half2(hx, hy);
    __half2 l = __halves2half2(__float2half_rn(lx), __float2half_rn(ly));
    hi = *(uint32_t*)&h;
    lo = *(uint32_t*)&l;
}

// ---------------------------------------------------------------------------
// fp16x3 tensor-core GEMM (R10 passing version, unchanged)
// ---------------------------------------------------------------------------
#define USTR 20
#define STG_U 4224
#define OFF_AH (STG_U)
#define OFF_AL (OFF_AH + 128*USTR)
#define OFF_BH (OFF_AL + 128*USTR)
#define OFF_BL (OFF_BH + 128*USTR)
#define HG_SMEM_U32 (OFF_BL + 128*USTR)
#define HG_SMEM_BYTES (HG_SMEM_U32 * 4)

__global__ __launch_bounds__(256) void hgemm3_kernel(
    int M, int N, int K,
    const float* __restrict__ A, const float* __restrict__ B, float* __restrict__ C)
{
    extern __shared__ uint32_t smu[];
    float*    stg = (float*)smu;
    uint32_t* Ah  = smu + OFF_AH;
    uint32_t* Al  = smu + OFF_AL;
    uint32_t* Bh  = smu + OFF_BH;
    uint32_t* Bl  = smu + OFF_BL;

    const int tid  = threadIdx.x;
    const int lane = tid & 31;
    const int wid  = tid >> 5;
    const int wm   = (wid & 3) * 32;
    const int wn   = (wid >> 2) * 64;
    const int g    = lane >> 2;
    const int tg   = lane & 3;

    const float* Abase = A + (size_t)blockIdx.y * 128 * K;
    const float* Bbase = B + (size_t)blockIdx.x * 128;

    float acc[2][8][4];
#pragma unroll
    for (int mt = 0; mt < 2; mt++)
#pragma unroll
        for (int nt = 0; nt < 8; nt++)
#pragma unroll
            for (int i = 0; i < 4; i++) acc[mt][nt][i] = 0.f;

    const int am = tid >> 3;
    const int ac = (tid & 7) * 4;
    const int bk0 = tid >> 5;
    const int bn  = (tid & 31) * 4;
    const int tn  = tid & 127;
    const int tkp = (tid >> 7) * 8;

    for (int k0 = 0; k0 < K; k0 += 32) {
#pragma unroll
        for (int it = 0; it < 4; ++it) {
            int m = it * 32 + am;
            float4 v = *(const float4*)(Abase + (size_t)m * K + k0 + ac);
            uint32_t h0, l0, h1, l1;
            split2(v.x, v.y, h0, l0);
            split2(v.z, v.w, h1, l1);
            int o = m * USTR + (ac >> 1);
            Ah[o] = h0; Ah[o + 1] = h1;
            Al[o] = l0; Al[o + 1] = l1;
        }
#pragma unroll
        for (int it = 0; it < 4; ++it) {
            int kk = it * 8 + bk0;
            *(float4*)&stg[kk * 132 + bn] =
                *(const float4*)(Bbase + (size_t)(k0 + kk) * N + bn);
        }
        __syncthreads();
#pragma unroll
        for (int j = 0; j < 8; ++j) {
            int kp = tkp + j;
            float x = stg[(2 * kp) * 132 + tn];
            float y = stg[(2 * kp + 1) * 132 + tn];
            uint32_t h, l;
            split2(x, y, h, l);
            Bh[tn * USTR + kp] = h;
            Bl[tn * USTR + kp] = l;
        }
        __syncthreads();

#pragma unroll
        for (int ks = 0; ks < 2; ++ks) {
            uint32_t ah[2][4], al[2][4];
#pragma unroll
            for (int mt = 0; mt < 2; mt++) {
                int r0 = (wm + mt * 16 + g) * USTR + ks * 8 + tg;
                int r8 = r0 + 8 * USTR;
                ah[mt][0] = Ah[r0];     ah[mt][1] = Ah[r8];
                ah[mt][2] = Ah[r0 + 4]; ah[mt][3] = Ah[r8 + 4];
                al[mt][0] = Al[r0];     al[mt][1] = Al[r8];
                al[mt][2] = Al[r0 + 4]; al[mt][3] = Al[r8 + 4];
            }
#pragma unroll
            for (int nt = 0; nt < 8; nt++) {
                int nb = (wn + nt * 8 + g) * USTR + ks * 8 + tg;
                uint32_t bh0 = Bh[nb], bh1 = Bh[nb + 4];
                uint32_t bl0 = Bl[nb], bl1 = Bl[nb + 4];
#pragma unroll
                for (int mt = 0; mt < 2; mt++) {
                    mma_f16(acc[mt][nt], ah[mt], bh0, bh1);
                    mma_f16(acc[mt][nt], ah[mt], bl0, bl1);
                    mma_f16(acc[mt][nt], al[mt], bh0, bh1);
                }
            }
        }
        __syncthreads();
    }

#pragma unroll
    for (int mt = 0; mt < 2; mt++) {
        int row = blockIdx.y * 128 + wm + mt * 16 + g;
#pragma unroll
        for (int nt = 0; nt < 8; nt++) {
            int col = blockIdx.x * 128 + wn + nt * 8 + tg * 2;
            *(float2*)(C + (size_t)row * N + col)       = make_float2(acc[mt][nt][0], acc[mt][nt][1]);
            *(float2*)(C + (size_t)(row + 8) * N + col) = make_float2(acc[mt][nt][2], acc[mt][nt][3]);
        }
    }
}

// ---------------------------------------------------------------------------
// RoPE (unchanged)
// ---------------------------------------------------------------------------
__global__ void rope_kernel(float* __restrict__ x, int heads)
{
    int idx = blockIdx.x * blockDim.x + threadIdx.x;
    int total = TT * heads * 64;
    if (idx >= total) return;
    int j  = idx & 63;
    int th = idx >> 6;
    int h  = th % heads;
    int t  = th / heads;
    int pos = HIST + (t & (QLEN - 1));

    float e = (float)(2 * j) * (1.0f / 128.0f);
    float freq = powf(1.0e6f, -e);
    float ang = (float)pos * freq;
    float s, c;
    sincosf(ang, &s, &c);

    size_t base = (size_t)t * heads * HD + (size_t)h * HD + j;
    float x0 = x[base];
    float x1 = x[base + 64];
    x[base]      = x0 * c - x1 * s;
    x[base + 64] = x1 * c + x0 * s;
}

// ---------------------------------------------------------------------------
// Tensor-core flash attention (fp16x3 QK^T and PV, fp32 online softmax)
// ---------------------------------------------------------------------------
#define U_QH 0
#define U_QL 4352
#define U_KH 8704
#define U_KL 13056
#define U_VH 17408
#define U_VL 22016
#define U_PH 26624
#define U_PL 28928
#define U_SS 31232
#define U_SA 35392
#define ATT_SMEM_U32 35456
#define ATT_SMEM_BYTES (ATT_SMEM_U32 * 4)

__global__ __launch_bounds__(256) void attn_tc_kernel(
    const float* __restrict__ kcache, const float* __restrict__ vcache)
{
    const int i0  = blockIdx.x * 64;
    const int h   = blockIdx.y;
    const int b   = blockIdx.z;
    const int kvh = h >> 2;
    const int tid = threadIdx.x;
    const int lane = tid & 31;
    const int wid  = tid >> 5;
    const int g    = lane >> 2;
    const int tg   = lane & 3;

    extern __shared__ uint32_t smu[];
    uint32_t* Qh = smu + U_QH;
    uint32_t* Ql = smu + U_QL;
    uint32_t* Kh = smu + U_KH;
    uint32_t* Kl = smu + U_KL;
    uint32_t* Vh = smu + U_VH;
    uint32_t* Vl = smu + U_VL;
    uint32_t* Ph = smu + U_PH;
    uint32_t* Pl = smu + U_PL;
    float*    sS = (float*)(smu + U_SS);
    float*    sA = (float*)(smu + U_SA);

    // ---- load + convert Q once (scale folded in) ----
#pragma unroll
    for (int it = 0; it < 8; ++it) {
        int idx = it * 256 + tid;
        int q  = idx >> 5;
        int d4 = (idx & 31) * 4;
        float4 v = *(const float4*)&g_q[(size_t)(b * QLEN + i0 + q) * HH + h * HD + d4];
        v.x *= SCALE; v.y *= SCALE; v.z *= SCALE; v.w *= SCALE;
        uint32_t h0, l0, h1, l1;
        split2(v.x, v.y, h0, l0);
        split2(v.z, v.w, h1, l1);
        int o = q * 68 + (d4 >> 1);
        Qh[o] = h0; Qh[o + 1] = h1;
        Ql[o] = l0; Ql[o + 1] = l1;
    }

    const int wmQ = (wid & 3) * 16;
    const int wnK = (wid >> 2) * 32;
    const int wnD = (wid >> 2) * 64;

    const int srow = tid >> 2, l4 = tid & 3;
    const int vjp = (wid << 2) + (lane >> 3);
    const int vd0 = lane & 7;
    const int pq = tid >> 2, pjb = (tid & 3) * 8;

    float m = NEGBIG, l = 0.f;
    float Oacc[8][4];
#pragma unroll
    for (int nt = 0; nt < 8; nt++)
#pragma unroll
        for (int i = 0; i < 4; i++) Oacc[nt][i] = 0.f;

    for (int t = 0; t < 17; ++t) {
        const int p0 = i0 + t * 64;
        __syncthreads();

        // ---- K tile convert ----
#pragma unroll
        for (int it = 0; it < 8; ++it) {
            int idx = it * 256 + tid;
            int r  = idx >> 5;
            int d4 = (idx & 31) * 4;
            int p  = p0 + r;
            const float* src = (p < HIST)
                ? kcache + ((size_t)(b * KVLEN + p) * NKV + kvh) * HD + d4
                : g_k + (size_t)(b * QLEN + (p - HIST)) * DKV + kvh * HD + d4;
            float4 v = *(const float4*)src;
            uint32_t h0, l0, h1, l1;
            split2(v.x, v.y, h0, l0);
            split2(v.z, v.w, h1, l1);
            int o = r * 68 + (d4 >> 1);
            Kh[o] = h0; Kh[o + 1] = h1;
            Kl[o] = l0; Kl[o + 1] = l1;
        }
        // ---- V tile convert (transposed) ----
        {
            int pj0 = p0 + 2 * vjp, pj1 = pj0 + 1;
            const float* s0 = (pj0 < HIST)
                ? vcache + ((size_t)(b * KVLEN + pj0) * NKV + kvh) * HD
                : g_v + (size_t)(b * QLEN + (pj0 - HIST)) * DKV + kvh * HD;
            const float* s1 = (pj1 < HIST)
                ? vcache + ((size_t)(b * KVLEN + pj1) * NKV + kvh) * HD
                : g_v + (size_t)(b * QLEN + (pj1 - HIST)) * DKV + kvh * HD;
#pragma unroll
            for (int i = 0; i < 16; ++i) {
                int d = vd0 + 8 * i;
                uint32_t hh, ll;
                split2(s0[d], s1[d], hh, ll);
                Vh[d * 36 + vjp] = hh;
                Vl[d * 36 + vjp] = ll;
            }
        }
        __syncthreads();

        // ---- QK^T mma ----
        float Sacc[4][4];
#pragma unroll
        for (int nt = 0; nt < 4; nt++)
#pragma unroll
            for (int i = 0; i < 4; i++) Sacc[nt][i] = 0.f;

#pragma unroll
        for (int ks = 0; ks < 8; ++ks) {
            int r0 = (wmQ + g) * 68 + ks * 8 + tg;
            int r8 = r0 + 8 * 68;
            uint32_t ah[4] = { Qh[r0], Qh[r8], Qh[r0 + 4], Qh[r8 + 4] };
            uint32_t al[4] = { Ql[r0], Ql[r8], Ql[r0 + 4], Ql[r8 + 4] };
#pragma unroll
            for (int nt = 0; nt < 4; nt++) {
                int nb = (wnK + nt * 8 + g) * 68 + ks * 8 + tg;
                uint32_t bh0 = Kh[nb], bh1 = Kh[nb + 4];
                uint32_t bl0 = Kl[nb], bl1 = Kl[nb + 4];
                mma_f16(Sacc[nt], ah, bh0, bh1);
                mma_f16(Sacc[nt], ah, bl0, bl1);
                mma_f16(Sacc[nt], al, bh0, bh1);
            }
        }

        // ---- write S with mask ----
        {
            int qi0 = wmQ + g, qi1 = qi0 + 8;
#pragma unroll
            for (int nt = 0; nt < 4; nt++) {
                int ki = wnK + nt * 8 + tg * 2;
                float c0 = Sacc[nt][0], c1 = Sacc[nt][1];
                float c2 = Sacc[nt][2], c3 = Sacc[nt][3];
                if (t == 0) {
                    if (!(ki     > qi0)) c0 = NEGBIG;
                    if (!(ki + 1 > qi0)) c1 = NEGBIG;
                    if (!(ki     > qi1)) c2 = NEGBIG;
                    if (!(ki + 1 > qi1)) c3 = NEGBIG;
                } else if (t == 16) {
                    if (!(ki     <= qi0)) c0 = NEGBIG;
                    if (!(ki + 1 <= qi0)) c1 = NEGBIG;
                    if (!(ki     <= qi1)) c2 = NEGBIG;
                    if (!(ki + 1 <= qi1)) c3 = NEGBIG;
                }
                sS[qi0 * 65 + ki] = c0; sS[qi0 * 65 + ki + 1] = c1;
                sS[qi1 * 65 + ki] = c2; sS[qi1 * 65 + ki + 1] = c3;
            }
        }
        __syncthreads();

        // ---- online softmax ----
        float tm = NEGBIG;
#pragma unroll
        for (int j = 0; j < 16; j++) tm = fmaxf(tm, sS[srow * 65 + l4 * 16 + j]);
        tm = fmaxf(tm, __shfl_xor_sync(0xffffffffu, tm, 1));
        tm = fmaxf(tm, __shfl_xor_sync(0xffffffffu, tm, 2));
        float mnew = fmaxf(m, tm);
        float alpha = __expf(m - mnew);
        float psum = 0.f;
#pragma unroll
        for (int j = 0; j < 16; j++) {
            float p = __expf(sS[srow * 65 + l4 * 16 + j] - mnew);
            sS[srow * 65 + l4 * 16 + j] = p;
            psum += p;
        }
        psum += __shfl_xor_sync(0xffffffffu, psum, 1);
        psum += __shfl_xor_sync(0xffffffffu, psum, 2);
        l = l * alpha + psum;
        m = mnew;
        if (l4 == 0) sA[srow] = alpha;
        __syncthreads();

        // ---- rescale O; convert P ----
        {
            float a0 = sA[wmQ + g], a1 = sA[wmQ + g + 8];
#pragma unroll
            for (int nt = 0; nt < 8; nt++) {
                Oacc[nt][0] *= a0; Oacc[nt][1] *= a0;
                Oacc[nt][2] *= a1; Oacc[nt][3] *= a1;
            }
        }
#pragma unroll
        for (int i = 0; i < 8; ++i) {
            int jp = pjb + i;
            uint32_t hh, ll;
            split2(sS[pq * 65 + 2 * jp], sS[pq * 65 + 2 * jp + 1], hh, ll);
            Ph[pq * 36 + jp] = hh;
            Pl[pq * 36 + jp] = ll;
        }
        __syncthreads();

        // ---- PV mma ----
#pragma unroll
        for (int ks = 0; ks < 4; ++ks) {
            int r0 = (wmQ + g) * 36 + ks * 8 + tg;
            int r8 = r0 + 8 * 36;
            uint32_t ph[4] = { Ph[r0], Ph[r8], Ph[r0 + 4], Ph[r8 + 4] };
            uint32_t pl[4] = { Pl[r0], Pl[r8], Pl[r0 + 4], Pl[r8 + 4] };
#pragma unroll
            for (int nt = 0; nt < 8; nt++) {
                int nb = (wnD + nt * 8 + g) * 36 + ks * 8 + tg;
                uint32_t vh0 = Vh[nb], vh1 = Vh[nb + 4];
                uint32_t vl0 = Vl[nb], vl1 = Vl[nb + 4];
                mma_f16(Oacc[nt], ph, vh0, vh1);
                mma_f16(Oacc[nt], ph, vl0, vl1);
                mma_f16(Oacc[nt], pl, vh0, vh1);
            }
        }
    }

    // ---- finalize ----
    __syncthreads();
    if (l4 == 0) sA[srow] = 1.0f / l;
    __syncthreads();
    {
        float i0v = sA[wmQ + g], i1v = sA[wmQ + g + 8];
        int row0 = b * QLEN + i0 + wmQ + g;
#pragma unroll
        for (int nt = 0; nt < 8; nt++) {
            int col = h * HD + wnD + nt * 8 + tg * 2;
            *(float2*)&g_o[(size_t)row0 * HH + col] =
                make_float2(Oacc[nt][0] * i0v, Oacc[nt][1] * i0v);
            *(float2*)&g_o[(size_t)(row0 + 8) * HH + col] =
                make_float2(Oacc[nt][2] * i1v, Oacc[nt][3] * i1v);
        }
    }
}

// ---------------------------------------------------------------------------
// Launch
// ---------------------------------------------------------------------------
extern "C" void kernel_launch(void* const* d_in, const int* in_sizes, int n_in,
                              void* d_out, int out_size)
{
    const float* hs = (const float*)d_in[0];
    const float* wq = (const float*)d_in[1];
    const float* wk = (const float*)d_in[2];
    const float* wv = (const float*)d_in[3];
    const float* wo = (const float*)d_in[4];
    const float* kc = (const float*)d_in[5];
    const float* vc = (const float*)d_in[6];

    float *qb, *kb, *vb, *ob;
    cudaGetSymbolAddress((void**)&qb, g_q);
    cudaGetSymbolAddress((void**)&kb, g_k);
    cudaGetSymbolAddress((void**)&vb, g_v);
    cudaGetSymbolAddress((void**)&ob, g_o);

    cudaFuncSetAttribute(hgemm3_kernel, cudaFuncAttributeMaxDynamicSharedMemorySize,
                         HG_SMEM_BYTES);
    cudaFuncSetAttribute(attn_tc_kernel, cudaFuncAttributeMaxDynamicSharedMemorySize,
                         ATT_SMEM_BYTES);

    dim3 gq(HH / 128, TT / 128);     // 32 x 32
    dim3 gkv(DKV / 128, TT / 128);   // 8 x 32

    hgemm3_kernel<<<gq,  256, HG_SMEM_BYTES>>>(TT, HH,  HH, hs, wq, qb);
    hgemm3_kernel<<<gkv, 256, HG_SMEM_BYTES>>>(TT, DKV, HH, hs, wk, kb);
    hgemm3_kernel<<<gkv, 256, HG_SMEM_BYTES>>>(TT, DKV, HH, hs, wv, vb);

    {
        int totq = TT * NHEADS * 64;
        rope_kernel<<<(totq + 255) / 256, 256>>>(qb, NHEADS);
        int totk = TT * NKV * 64;
        rope_kernel<<<(totk + 255) / 256, 256>>>(kb, NKV);
    }

    dim3 ga(QLEN / 64, NHEADS, BATCH);
    attn_tc_kernel<<<ga, 256, ATT_SMEM_BYTES>>>(kc, vc);

    hgemm3_kernel<<<gq, 256, HG_SMEM_BYTES>>>(TT, HH, HH, ob, wo, (float*)d_out);
}

// round 16
// speedup vs baseline: 2.4808x; 1.0874x over previous
#include <cuda_runtime.h>
#include <cuda_fp16.h>
#include <math.h>
#include <stdint.h>

// ---------------------------------------------------------------------------
// Problem constants
// ---------------------------------------------------------------------------
#define TT     4096
#define HH     4096
#define NHEADS 32
#define NKV    8
#define HD     128
#define BATCH  4
#define QLEN   1024
#define HIST   1024
#define KVLEN  2048
#define WINDOW 1024
#define DKV    (NKV*HD)
#define SCALE  0.08838834764831845f
#define NEGBIG (-3.0e38f)

// ---------------------------------------------------------------------------
// Scratch
// ---------------------------------------------------------------------------
__device__ float g_q[(size_t)TT * HH];
__device__ float g_k[(size_t)TT * DKV];
__device__ float g_v[(size_t)TT * DKV];
__device__ float g_o[(size_t)TT * HH];

// pre-converted fp16 hi/lo buffers
__device__ __half c_ah[(size_t)TT * HH];       // A operand (hs, then g_o)
__device__ __half c_al[(size_t)TT * HH];
__device__ __half w_qh[(size_t)HH * HH];       // weights, TRANSPOSED to [N][K]
__device__ __half w_ql[(size_t)HH * HH];
__device__ __half w_kh[(size_t)DKV * HH];
__device__ __half w_kl[(size_t)DKV * HH];
__device__ __half w_vh[(size_t)DKV * HH];
__device__ __half w_vl[(size_t)DKV * HH];
__device__ __half w_oh[(size_t)HH * HH];
__device__ __half w_ol[(size_t)HH * HH];

// ---------------------------------------------------------------------------
// helpers
// ---------------------------------------------------------------------------
__device__ __forceinline__ void mma_f16(float* d, const uint32_t* a, uint32_t b0, uint32_t b1)
{
    asm volatile(
        "mma.sync.aligned.m16n8k16.row.col.f32.f16.f16.f32 "
        "{%0,%1,%2,%3}, {%4,%5,%6,%7}, {%8,%9}, {%0,%1,%2,%3};\n"
        : "+f"(d[0]), "+f"(d[1]), "+f"(d[2]), "+f"(d[3])
        : "r"(a[0]), "r"(a[1]), "r"(a[2]), "r"(a[3]), "r"(b0), "r"(b1));
}

__device__ __forceinline__ void split2(float x, float y, uint32_t& hi, uint32_t& lo)
{
    __half hx = __float2half_rn(x);
    __half hy = __float2half_rn(y);
    float lx = x - __half2float(hx);
    float ly = y - __half2float(hy);
    __half2 h = __halves2half2(hx, hy);
    __half2 l = __halves2half2(__float2half_rn(lx), __float2half_rn(ly));
    hi = *(uint32_t*)&h;
    lo = *(uint32_t*)&l;
}

__device__ __forceinline__ uint32_t smem_u32(const void* p) {
    uint32_t a;
    asm("{ .reg .u64 t; cvta.to.shared.u64 t, %1; cvt.u32.u64 %0, t; }" : "=r"(a) : "l"(p));
    return a;
}

__device__ __forceinline__ void cp16(uint32_t dst, const void* src) {
    asm volatile("cp.async.cg.shared.global [%0], [%1], 16;\n" :: "r"(dst), "l"(src));
}

// ---------------------------------------------------------------------------
// Convert kernels
// ---------------------------------------------------------------------------
// elementwise split: x -> (hi fp16, lo fp16), same layout
__global__ __launch_bounds__(256) void conv_a_kernel(
    const float* __restrict__ x, __half* __restrict__ h, __half* __restrict__ l, int n4)
{
    int i = blockIdx.x * 256 + threadIdx.x;
    if (i >= n4) return;
    float4 v = *(const float4*)(x + (size_t)i * 4);
    uint32_t h0, l0, h1, l1;
    split2(v.x, v.y, h0, l0);
    split2(v.z, v.w, h1, l1);
    uint2 hh = make_uint2(h0, h1);
    uint2 ll = make_uint2(l0, l1);
    *(uint2*)(h + (size_t)i * 4) = hh;
    *(uint2*)(l + (size_t)i * 4) = ll;
}

// transpose + split: W[K][N] -> T[N][K] hi/lo
__global__ __launch_bounds__(256) void conv_b_kernel(
    const float* __restrict__ W, __half* __restrict__ Th, __half* __restrict__ Tl,
    int K, int N)
{
    __shared__ float t[32][33];
    const int n0 = blockIdx.x * 32;
    const int k0 = blockIdx.y * 32;
    const int tx = threadIdx.x & 31;
    const int ty = threadIdx.x >> 5;   // 0..7
#pragma unroll
    for (int j = 0; j < 4; ++j) {
        int kk = ty + j * 8;
        t[kk][tx] = W[(size_t)(k0 + kk) * N + n0 + tx];
    }
    __syncthreads();
#pragma unroll
    for (int j = 0; j < 4; ++j) {
        int nn = ty + j * 8;
        float v = t[tx][nn];   // = W[k0+tx][n0+nn]
        __half hh = __float2half_rn(v);
        __half ll = __float2half_rn(v - __half2float(hh));
        size_t o = (size_t)(n0 + nn) * K + k0 + tx;
        Th[o] = hh;
        Tl[o] = ll;
    }
}

// ---------------------------------------------------------------------------
// Pre-converted fp16x3 GEMM with cp.async double buffering.
// C[M,N] = A[M,K] @ B^T[N,K]  (B given transposed, hi/lo halves)
// CTA 128x128, chunk 32 k, 256 thr, 8 warps (4M x 2N).
// smem: 2 stages x (Ah,Al,Bh,Bl)[128][20 u32]  (16 used + 4 pad)
// ---------------------------------------------------------------------------
#define PSTR 20
#define TILE_U (128*PSTR)          // 2560 u32 per tile
#define STAGE_U (4*TILE_U)         // 10240 u32 per stage
#define PG_SMEM_BYTES (2*STAGE_U*4)  // 81920

__global__ __launch_bounds__(256) void hgemm_pre_kernel(
    int M, int N, int K,
    const __half* __restrict__ Ah_g, const __half* __restrict__ Al_g,
    const __half* __restrict__ Bh_g, const __half* __restrict__ Bl_g,
    float* __restrict__ C)
{
    extern __shared__ uint32_t smu[];
    const uint32_t sbase = smem_u32(smu);

    const int tid  = threadIdx.x;
    const int lane = tid & 31;
    const int wid  = tid >> 5;
    const int wm   = (wid & 3) * 32;
    const int wn   = (wid >> 2) * 64;
    const int g    = lane >> 2;
    const int tg   = lane & 3;

    const int aRow0 = blockIdx.y * 128;
    const int bRow0 = blockIdx.x * 128;

    // cp.async mapping: per tile, chunk c in [0,512): row=c>>2, q=c&3 (16B each)
    const int r0c = tid >> 2, q0 = tid & 3;          // chunks 0..255
    const int r1c = 64 + (tid >> 2);                 // chunks 256..511

    float acc[2][8][4];
#pragma unroll
    for (int mt = 0; mt < 2; mt++)
#pragma unroll
        for (int nt = 0; nt < 8; nt++)
#pragma unroll
            for (int i = 0; i < 4; i++) acc[mt][nt][i] = 0.f;

    const int nIter = K / 32;

    // ---- stage loader (issues 8 cp.async per thread + commit) ----
    auto load_stage = [&](int stage, int k0) {
        uint32_t sb = sbase + (uint32_t)(stage * STAGE_U) * 4;
        const __half* srcA_h = Ah_g + (size_t)(aRow0 + r0c) * K + k0 + q0 * 8;
        const __half* srcA_l = Al_g + (size_t)(aRow0 + r0c) * K + k0 + q0 * 8;
        const __half* srcB_h = Bh_g + (size_t)(bRow0 + r0c) * K + k0 + q0 * 8;
        const __half* srcB_l = Bl_g + (size_t)(bRow0 + r0c) * K + k0 + q0 * 8;
        uint32_t d0 = sb + (uint32_t)(r0c * PSTR + q0 * 4) * 4;
        cp16(d0,                srcA_h);
        cp16(d0 + TILE_U * 4,   srcA_l);
        cp16(d0 + 2*TILE_U * 4, srcB_h);
        cp16(d0 + 3*TILE_U * 4, srcB_l);
        const __half* srcA_h2 = Ah_g + (size_t)(aRow0 + r1c) * K + k0 + q0 * 8;
        const __half* srcA_l2 = Al_g + (size_t)(aRow0 + r1c) * K + k0 + q0 * 8;
        const __half* srcB_h2 = Bh_g + (size_t)(bRow0 + r1c) * K + k0 + q0 * 8;
        const __half* srcB_l2 = Bl_g + (size_t)(bRow0 + r1c) * K + k0 + q0 * 8;
        uint32_t d1 = sb + (uint32_t)(r1c * PSTR + q0 * 4) * 4;
        cp16(d1,                srcA_h2);
        cp16(d1 + TILE_U * 4,   srcA_l2);
        cp16(d1 + 2*TILE_U * 4, srcB_h2);
        cp16(d1 + 3*TILE_U * 4, srcB_l2);
        asm volatile("cp.async.commit_group;\n" ::: "memory");
    };

    load_stage(0, 0);

    for (int it = 0; it < nIter; ++it) {
        const int cur = it & 1;
        if (it + 1 < nIter) {
            load_stage(cur ^ 1, (it + 1) * 32);
            asm volatile("cp.async.wait_group 1;\n" ::: "memory");
        } else {
            asm volatile("cp.async.wait_group 0;\n" ::: "memory");
        }
        __syncthreads();

        uint32_t* Ah = smu + cur * STAGE_U;
        uint32_t* Al = Ah + TILE_U;
        uint32_t* Bh = Al + TILE_U;
        uint32_t* Bl = Bh + TILE_U;

#pragma unroll
        for (int ks = 0; ks < 2; ++ks) {
            uint32_t ah[2][4], al[2][4];
#pragma unroll
            for (int mt = 0; mt < 2; mt++) {
                int r0 = (wm + mt * 16 + g) * PSTR + ks * 8 + tg;
                int r8 = r0 + 8 * PSTR;
                ah[mt][0] = Ah[r0];     ah[mt][1] = Ah[r8];
                ah[mt][2] = Ah[r0 + 4]; ah[mt][3] = Ah[r8 + 4];
                al[mt][0] = Al[r0];     al[mt][1] = Al[r8];
                al[mt][2] = Al[r0 + 4]; al[mt][3] = Al[r8 + 4];
            }
#pragma unroll
            for (int nt = 0; nt < 8; nt++) {
                int nb = (wn + nt * 8 + g) * PSTR + ks * 8 + tg;
                uint32_t bh0 = Bh[nb], bh1 = Bh[nb + 4];
                uint32_t bl0 = Bl[nb], bl1 = Bl[nb + 4];
#pragma unroll
                for (int mt = 0; mt < 2; mt++) {
                    mma_f16(acc[mt][nt], ah[mt], bh0, bh1);
                    mma_f16(acc[mt][nt], ah[mt], bl0, bl1);
                    mma_f16(acc[mt][nt], al[mt], bh0, bh1);
                }
            }
        }
        __syncthreads();
    }

#pragma unroll
    for (int mt = 0; mt < 2; mt++) {
        int row = blockIdx.y * 128 + wm + mt * 16 + g;
#pragma unroll
        for (int nt = 0; nt < 8; nt++) {
            int col = blockIdx.x * 128 + wn + nt * 8 + tg * 2;
            *(float2*)(C + (size_t)row * N + col)       = make_float2(acc[mt][nt][0], acc[mt][nt][1]);
            *(float2*)(C + (size_t)(row + 8) * N + col) = make_float2(acc[mt][nt][2], acc[mt][nt][3]);
        }
    }
}

// ---------------------------------------------------------------------------
// RoPE (unchanged)
// ---------------------------------------------------------------------------
__global__ void rope_kernel(float* __restrict__ x, int heads)
{
    int idx = blockIdx.x * blockDim.x + threadIdx.x;
    int total = TT * heads * 64;
    if (idx >= total) return;
    int j  = idx & 63;
    int th = idx >> 6;
    int h  = th % heads;
    int t  = th / heads;
    int pos = HIST + (t & (QLEN - 1));

    float e = (float)(2 * j) * (1.0f / 128.0f);
    float freq = powf(1.0e6f, -e);
    float ang = (float)pos * freq;
    float s, c;
    sincosf(ang, &s, &c);

    size_t base = (size_t)t * heads * HD + (size_t)h * HD + j;
    float x0 = x[base];
    float x1 = x[base + 64];
    x[base]      = x0 * c - x1 * s;
    x[base + 64] = x1 * c + x0 * s;
}

// ---------------------------------------------------------------------------
// Tensor-core flash attention (R13 passing version, unchanged)
// ---------------------------------------------------------------------------
#define U_QH 0
#define U_QL 4352
#define U_KH 8704
#define U_KL 13056
#define U_VH 17408
#define U_VL 22016
#define U_PH 26624
#define U_PL 28928
#define U_SS 31232
#define U_SA 35392
#define ATT_SMEM_U32 35456
#define ATT_SMEM_BYTES (ATT_SMEM_U32 * 4)

__global__ __launch_bounds__(256) void attn_tc_kernel(
    const float* __restrict__ kcache, const float* __restrict__ vcache)
{
    const int i0  = blockIdx.x * 64;
    const int h   = blockIdx.y;
    const int b   = blockIdx.z;
    const int kvh = h >> 2;
    const int tid = threadIdx.x;
    const int lane = tid & 31;
    const int wid  = tid >> 5;
    const int g    = lane >> 2;
    const int tg   = lane & 3;

    extern __shared__ uint32_t smu[];
    uint32_t* Qh = smu + U_QH;
    uint32_t* Ql = smu + U_QL;
    uint32_t* Kh = smu + U_KH;
    uint32_t* Kl = smu + U_KL;
    uint32_t* Vh = smu + U_VH;
    uint32_t* Vl = smu + U_VL;
    uint32_t* Ph = smu + U_PH;
    uint32_t* Pl = smu + U_PL;
    float*    sS = (float*)(smu + U_SS);
    float*    sA = (float*)(smu + U_SA);

#pragma unroll
    for (int it = 0; it < 8; ++it) {
        int idx = it * 256 + tid;
        int q  = idx >> 5;
        int d4 = (idx & 31) * 4;
        float4 v = *(const float4*)&g_q[(size_t)(b * QLEN + i0 + q) * HH + h * HD + d4];
        v.x *= SCALE; v.y *= SCALE; v.z *= SCALE; v.w *= SCALE;
        uint32_t h0, l0, h1, l1;
        split2(v.x, v.y, h0, l0);
        split2(v.z, v.w, h1, l1);
        int o = q * 68 + (d4 >> 1);
        Qh[o] = h0; Qh[o + 1] = h1;
        Ql[o] = l0; Ql[o + 1] = l1;
    }

    const int wmQ = (wid & 3) * 16;
    const int wnK = (wid >> 2) * 32;
    const int wnD = (wid >> 2) * 64;

    const int srow = tid >> 2, l4 = tid & 3;
    const int vjp = (wid << 2) + (lane >> 3);
    const int vd0 = lane & 7;
    const int pq = tid >> 2, pjb = (tid & 3) * 8;

    float m = NEGBIG, l = 0.f;
    float Oacc[8][4];
#pragma unroll
    for (int nt = 0; nt < 8; nt++)
#pragma unroll
        for (int i = 0; i < 4; i++) Oacc[nt][i] = 0.f;

    for (int t = 0; t < 17; ++t) {
        const int p0 = i0 + t * 64;
        __syncthreads();

#pragma unroll
        for (int it = 0; it < 8; ++it) {
            int idx = it * 256 + tid;
            int r  = idx >> 5;
            int d4 = (idx & 31) * 4;
            int p  = p0 + r;
            const float* src = (p < HIST)
                ? kcache + ((size_t)(b * KVLEN + p) * NKV + kvh) * HD + d4
                : g_k + (size_t)(b * QLEN + (p - HIST)) * DKV + kvh * HD + d4;
            float4 v = *(const float4*)src;
            uint32_t h0, l0, h1, l1;
            split2(v.x, v.y, h0, l0);
            split2(v.z, v.w, h1, l1);
            int o = r * 68 + (d4 >> 1);
            Kh[o] = h0; Kh[o + 1] = h1;
            Kl[o] = l0; Kl[o + 1] = l1;
        }
        {
            int pj0 = p0 + 2 * vjp, pj1 = pj0 + 1;
            const float* s0 = (pj0 < HIST)
                ? vcache + ((size_t)(b * KVLEN + pj0) * NKV + kvh) * HD
                : g_v + (size_t)(b * QLEN + (pj0 - HIST)) * DKV + kvh * HD;
            const float* s1 = (pj1 < HIST)
                ? vcache + ((size_t)(b * KVLEN + pj1) * NKV + kvh) * HD
                : g_v + (size_t)(b * QLEN + (pj1 - HIST)) * DKV + kvh * HD;
#pragma unroll
            for (int i = 0; i < 16; ++i) {
                int d = vd0 + 8 * i;
                uint32_t hh, ll;
                split2(s0[d], s1[d], hh, ll);
                Vh[d * 36 + vjp] = hh;
                Vl[d * 36 + vjp] = ll;
            }
        }
        __syncthreads();

        float Sacc[4][4];
#pragma unroll
        for (int nt = 0; nt < 4; nt++)
#pragma unroll
            for (int i = 0; i < 4; i++) Sacc[nt][i] = 0.f;

#pragma unroll
        for (int ks = 0; ks < 8; ++ks) {
            int r0 = (wmQ + g) * 68 + ks * 8 + tg;
            int r8 = r0 + 8 * 68;
            uint32_t ah[4] = { Qh[r0], Qh[r8], Qh[r0 + 4], Qh[r8 + 4] };
            uint32_t al[4] = { Ql[r0], Ql[r8], Ql[r0 + 4], Ql[r8 + 4] };
#pragma unroll
            for (int nt = 0; nt < 4; nt++) {
                int nb = (wnK + nt * 8 + g) * 68 + ks * 8 + tg;
                uint32_t bh0 = Kh[nb], bh1 = Kh[nb + 4];
                uint32_t bl0 = Kl[nb], bl1 = Kl[nb + 4];
                mma_f16(Sacc[nt], ah, bh0, bh1);
                mma_f16(Sacc[nt], ah, bl0, bl1);
                mma_f16(Sacc[nt], al, bh0, bh1);
            }
        }

        {
            int qi0 = wmQ + g, qi1 = qi0 + 8;
#pragma unroll
            for (int nt = 0; nt < 4; nt++) {
                int ki = wnK + nt * 8 + tg * 2;
                float c0 = Sacc[nt][0], c1 = Sacc[nt][1];
                float c2 = Sacc[nt][2], c3 = Sacc[nt][3];
                if (t == 0) {
                    if (!(ki     > qi0)) c0 = NEGBIG;
                    if (!(ki + 1 > qi0)) c1 = NEGBIG;
                    if (!(ki     > qi1)) c2 = NEGBIG;
                    if (!(ki + 1 > qi1)) c3 = NEGBIG;
                } else if (t == 16) {
                    if (!(ki     <= qi0)) c0 = NEGBIG;
                    if (!(ki + 1 <= qi0)) c1 = NEGBIG;
                    if (!(ki     <= qi1)) c2 = NEGBIG;
                    if (!(ki + 1 <= qi1)) c3 = NEGBIG;
                }
                sS[qi0 * 65 + ki] = c0; sS[qi0 * 65 + ki + 1] = c1;
                sS[qi1 * 65 + ki] = c2; sS[qi1 * 65 + ki + 1] = c3;
            }
        }
        __syncthreads();

        float tm = NEGBIG;
#pragma unroll
        for (int j = 0; j < 16; j++) tm = fmaxf(tm, sS[srow * 65 + l4 * 16 + j]);
        tm = fmaxf(tm, __shfl_xor_sync(0xffffffffu, tm, 1));
        tm = fmaxf(tm, __shfl_xor_sync(0xffffffffu, tm, 2));
        float mnew = fmaxf(m, tm);
        float alpha = __expf(m - mnew);
        float psum = 0.f;
#pragma unroll
        for (int j = 0; j < 16; j++) {
            float p = __expf(sS[srow * 65 + l4 * 16 + j] - mnew);
            sS[srow * 65 + l4 * 16 + j] = p;
            psum += p;
        }
        psum += __shfl_xor_sync(0xffffffffu, psum, 1);
        psum += __shfl_xor_sync(0xffffffffu, psum, 2);
        l = l * alpha + psum;
        m = mnew;
        if (l4 == 0) sA[srow] = alpha;
        __syncthreads();

        {
            float a0 = sA[wmQ + g], a1 = sA[wmQ + g + 8];
#pragma unroll
            for (int nt = 0; nt < 8; nt++) {
                Oacc[nt][0] *= a0; Oacc[nt][1] *= a0;
                Oacc[nt][2] *= a1; Oacc[nt][3] *= a1;
            }
        }
#pragma unroll
        for (int i = 0; i < 8; ++i) {
            int jp = pjb + i;
            uint32_t hh, ll;
            split2(sS[pq * 65 + 2 * jp], sS[pq * 65 + 2 * jp + 1], hh, ll);
            Ph[pq * 36 + jp] = hh;
            Pl[pq * 36 + jp] = ll;
        }
        __syncthreads();

#pragma unroll
        for (int ks = 0; ks < 4; ++ks) {
            int r0 = (wmQ + g) * 36 + ks * 8 + tg;
            int r8 = r0 + 8 * 36;
            uint32_t ph[4] = { Ph[r0], Ph[r8], Ph[r0 + 4], Ph[r8 + 4] };
            uint32_t pl[4] = { Pl[r0], Pl[r8], Pl[r0 + 4], Pl[r8 + 4] };
#pragma unroll
            for (int nt = 0; nt < 8; nt++) {
                int nb = (wnD + nt * 8 + g) * 36 + ks * 8 + tg;
                uint32_t vh0 = Vh[nb], vh1 = Vh[nb + 4];
                uint32_t vl0 = Vl[nb], vl1 = Vl[nb + 4];
                mma_f16(Oacc[nt], ph, vh0, vh1);
                mma_f16(Oacc[nt], ph, vl0, vl1);
                mma_f16(Oacc[nt], pl, vh0, vh1);
            }
        }
    }

    __syncthreads();
    if (l4 == 0) sA[srow] = 1.0f / l;
    __syncthreads();
    {
        float i0v = sA[wmQ + g], i1v = sA[wmQ + g + 8];
        int row0 = b * QLEN + i0 + wmQ + g;
#pragma unroll
        for (int nt = 0; nt < 8; nt++) {
            int col = h * HD + wnD + nt * 8 + tg * 2;
            *(float2*)&g_o[(size_t)row0 * HH + col] =
                make_float2(Oacc[nt][0] * i0v, Oacc[nt][1] * i0v);
            *(float2*)&g_o[(size_t)(row0 + 8) * HH + col] =
                make_float2(Oacc[nt][2] * i1v, Oacc[nt][3] * i1v);
        }
    }
}

// ---------------------------------------------------------------------------
// Launch
// ---------------------------------------------------------------------------
extern "C" void kernel_launch(void* const* d_in, const int* in_sizes, int n_in,
                              void* d_out, int out_size)
{
    const float* hs = (const float*)d_in[0];
    const float* wq = (const float*)d_in[1];
    const float* wk = (const float*)d_in[2];
    const float* wv = (const float*)d_in[3];
    const float* wo = (const float*)d_in[4];
    const float* kc = (const float*)d_in[5];
    const float* vc = (const float*)d_in[6];

    float *qb, *kb, *vb, *ob;
    cudaGetSymbolAddress((void**)&qb, g_q);
    cudaGetSymbolAddress((void**)&kb, g_k);
    cudaGetSymbolAddress((void**)&vb, g_v);
    cudaGetSymbolAddress((void**)&ob, g_o);
    __half *cah, *cal, *wqh, *wql, *wkh, *wkl, *wvh, *wvl, *woh, *wol;
    cudaGetSymbolAddress((void**)&cah, c_ah);
    cudaGetSymbolAddress((void**)&cal, c_al);
    cudaGetSymbolAddress((void**)&wqh, w_qh);
    cudaGetSymbolAddress((void**)&wql, w_ql);
    cudaGetSymbolAddress((void**)&wkh, w_kh);
    cudaGetSymbolAddress((void**)&wkl, w_kl);
    cudaGetSymbolAddress((void**)&wvh, w_vh);
    cudaGetSymbolAddress((void**)&wvl, w_vl);
    cudaGetSymbolAddress((void**)&woh, w_oh);
    cudaGetSymbolAddress((void**)&wol, w_ol);

    cudaFuncSetAttribute(hgemm_pre_kernel, cudaFuncAttributeMaxDynamicSharedMemorySize,
                         PG_SMEM_BYTES);
    cudaFuncSetAttribute(attn_tc_kernel, cudaFuncAttributeMaxDynamicSharedMemorySize,
                         ATT_SMEM_BYTES);

    const int n4hh = TT * HH / 4;   // 4.19M

    // convert A (hidden states) and weights
    conv_a_kernel<<<(n4hh + 255) / 256, 256>>>(hs, cah, cal, n4hh);
    conv_b_kernel<<<dim3(HH / 32, HH / 32),  256>>>(wq, wqh, wql, HH, HH);
    conv_b_kernel<<<dim3(DKV / 32, HH / 32), 256>>>(wk, wkh, wkl, HH, DKV);
    conv_b_kernel<<<dim3(DKV / 32, HH / 32), 256>>>(wv, wvh, wvl, HH, DKV);
    conv_b_kernel<<<dim3(HH / 32, HH / 32),  256>>>(wo, woh, wol, HH, HH);

    dim3 gq(HH / 128, TT / 128);     // 32 x 32
    dim3 gkv(DKV / 128, TT / 128);   // 8 x 32

    hgemm_pre_kernel<<<gq,  256, PG_SMEM_BYTES>>>(TT, HH,  HH, cah, cal, wqh, wql, qb);
    hgemm_pre_kernel<<<gkv, 256, PG_SMEM_BYTES>>>(TT, DKV, HH, cah, cal, wkh, wkl, kb);
    hgemm_pre_kernel<<<gkv, 256, PG_SMEM_BYTES>>>(TT, DKV, HH, cah, cal, wvh, wvl, vb);

    {
        int totq = TT * NHEADS * 64;
        rope_kernel<<<(totq + 255) / 256, 256>>>(qb, NHEADS);
        int totk = TT * NKV * 64;
        rope_kernel<<<(totk + 255) / 256, 256>>>(kb, NKV);
    }

    dim3 ga(QLEN / 64, NHEADS, BATCH);
    attn_tc_kernel<<<ga, 256, ATT_SMEM_BYTES>>>(kc, vc);

    // convert attention output, then O-projection into d_out
    conv_a_kernel<<<(n4hh + 255) / 256, 256>>>(ob, cah, cal, n4hh);
    hgemm_pre_kernel<<<gq, 256, PG_SMEM_BYTES>>>(TT, HH, HH, cah, cal, woh, wol, (float*)d_out);
}

// round 17
// speedup vs baseline: 3.0806x; 1.2418x over previous
#include <cuda_runtime.h>
#include <cuda_fp16.h>
#include <math.h>
#include <stdint.h>

// ---------------------------------------------------------------------------
// Problem constants
// ---------------------------------------------------------------------------
#define TT     4096
#define HH     4096
#define NHEADS 32
#define NKV    8
#define HD     128
#define BATCH  4
#define QLEN   1024
#define HIST   1024
#define KVLEN  2048
#define WINDOW 1024
#define DKV    (NKV*HD)
#define SCALE  0.08838834764831845f
#define NEGBIG (-3.0e38f)

// ---------------------------------------------------------------------------
// Scratch
// ---------------------------------------------------------------------------
__device__ float g_q[(size_t)TT * HH];
__device__ float g_k[(size_t)TT * DKV];
__device__ float g_v[(size_t)TT * DKV];
__device__ float g_o[(size_t)TT * HH];

// pre-converted fp16 buffers: A exact (hi+lo), B single fp16 (transposed)
__device__ __half c_ah[(size_t)TT * HH];
__device__ __half c_al[(size_t)TT * HH];
__device__ __half w_qh[(size_t)HH * HH];
__device__ __half w_kh[(size_t)DKV * HH];
__device__ __half w_vh[(size_t)DKV * HH];
__device__ __half w_oh[(size_t)HH * HH];

// ---------------------------------------------------------------------------
// helpers
// ---------------------------------------------------------------------------
__device__ __forceinline__ void mma_f16(float* d, const uint32_t* a, uint32_t b0, uint32_t b1)
{
    asm volatile(
        "mma.sync.aligned.m16n8k16.row.col.f32.f16.f16.f32 "
        "{%0,%1,%2,%3}, {%4,%5,%6,%7}, {%8,%9}, {%0,%1,%2,%3};\n"
        : "+f"(d[0]), "+f"(d[1]), "+f"(d[2]), "+f"(d[3])
        : "r"(a[0]), "r"(a[1]), "r"(a[2]), "r"(a[3]), "r"(b0), "r"(b1));
}

__device__ __forceinline__ void split2(float x, float y, uint32_t& hi, uint32_t& lo)
{
    __half hx = __float2half_rn(x);
    __half hy = __float2half_rn(y);
    float lx = x - __half2float(hx);
    float ly = y - __half2float(hy);
    __half2 h = __halves2half2(hx, hy);
    __half2 l = __halves2half2(__float2half_rn(lx), __float2half_rn(ly));
    hi = *(uint32_t*)&h;
    lo = *(uint32_t*)&l;
}

__device__ __forceinline__ uint32_t smem_u32(const void* p) {
    uint32_t a;
    asm("{ .reg .u64 t; cvta.to.shared.u64 t, %1; cvt.u32.u64 %0, t; }" : "=r"(a) : "l"(p));
    return a;
}

__device__ __forceinline__ void cp16(uint32_t dst, const void* src) {
    asm volatile("cp.async.cg.shared.global [%0], [%1], 16;\n" :: "r"(dst), "l"(src));
}

// ---------------------------------------------------------------------------
// Convert kernels
// ---------------------------------------------------------------------------
__global__ __launch_bounds__(256) void conv_a_kernel(
    const float* __restrict__ x, __half* __restrict__ h, __half* __restrict__ l, int n4)
{
    int i = blockIdx.x * 256 + threadIdx.x;
    if (i >= n4) return;
    float4 v = *(const float4*)(x + (size_t)i * 4);
    uint32_t h0, l0, h1, l1;
    split2(v.x, v.y, h0, l0);
    split2(v.z, v.w, h1, l1);
    *(uint2*)(h + (size_t)i * 4) = make_uint2(h0, h1);
    *(uint2*)(l + (size_t)i * 4) = make_uint2(l0, l1);
}

// transpose + round: W[K][N] -> T[N][K] (single fp16)
__global__ __launch_bounds__(256) void conv_b_kernel(
    const float* __restrict__ W, __half* __restrict__ Th, int K, int N)
{
    __shared__ float t[32][33];
    const int n0 = blockIdx.x * 32;
    const int k0 = blockIdx.y * 32;
    const int tx = threadIdx.x & 31;
    const int ty = threadIdx.x >> 5;
#pragma unroll
    for (int j = 0; j < 4; ++j) {
        int kk = ty + j * 8;
        t[kk][tx] = W[(size_t)(k0 + kk) * N + n0 + tx];
    }
    __syncthreads();
#pragma unroll
    for (int j = 0; j < 4; ++j) {
        int nn = ty + j * 8;
        Th[(size_t)(n0 + nn) * K + k0 + tx] = __float2half_rn(t[tx][nn]);
    }
}

// ---------------------------------------------------------------------------
// 2-term fp16 GEMM (A exact hi/lo, B fp16) with cp.async double buffering.
// C[M,N] = A[M,K] @ B^T[N,K];  C = ah*bh + al*bh  (= a * fp16(b))
// CTA 128x128, chunk 32 k, 256 thr, 8 warps (4M x 2N).
// smem: 2 stages x (Ah,Al,Bh)[128][20 u32]
// ---------------------------------------------------------------------------
#define PSTR 20
#define TILE_U (128*PSTR)            // 2560 u32
#define STAGE_U (3*TILE_U)           // 7680 u32
#define PG_SMEM_BYTES (2*STAGE_U*4)  // 61440

__global__ __launch_bounds__(256) void hgemm2_kernel(
    int M, int N, int K,
    const __half* __restrict__ Ah_g, const __half* __restrict__ Al_g,
    const __half* __restrict__ Bh_g,
    float* __restrict__ C)
{
    extern __shared__ uint32_t smu[];
    const uint32_t sbase = smem_u32(smu);

    const int tid  = threadIdx.x;
    const int lane = tid & 31;
    const int wid  = tid >> 5;
    const int wm   = (wid & 3) * 32;
    const int wn   = (wid >> 2) * 64;
    const int g    = lane >> 2;
    const int tg   = lane & 3;

    const int aRow0 = blockIdx.y * 128;
    const int bRow0 = blockIdx.x * 128;

    const int r0c = tid >> 2, q0 = tid & 3;
    const int r1c = 64 + (tid >> 2);

    float acc[2][8][4];
#pragma unroll
    for (int mt = 0; mt < 2; mt++)
#pragma unroll
        for (int nt = 0; nt < 8; nt++)
#pragma unroll
            for (int i = 0; i < 4; i++) acc[mt][nt][i] = 0.f;

    const int nIter = K / 32;

    auto load_stage = [&](int stage, int k0) {
        uint32_t sb = sbase + (uint32_t)(stage * STAGE_U) * 4;
        uint32_t d0 = sb + (uint32_t)(r0c * PSTR + q0 * 4) * 4;
        cp16(d0,                Ah_g + (size_t)(aRow0 + r0c) * K + k0 + q0 * 8);
        cp16(d0 + TILE_U * 4,   Al_g + (size_t)(aRow0 + r0c) * K + k0 + q0 * 8);
        cp16(d0 + 2*TILE_U * 4, Bh_g + (size_t)(bRow0 + r0c) * K + k0 + q0 * 8);
        uint32_t d1 = sb + (uint32_t)(r1c * PSTR + q0 * 4) * 4;
        cp16(d1,                Ah_g + (size_t)(aRow0 + r1c) * K + k0 + q0 * 8);
        cp16(d1 + TILE_U * 4,   Al_g + (size_t)(aRow0 + r1c) * K + k0 + q0 * 8);
        cp16(d1 + 2*TILE_U * 4, Bh_g + (size_t)(bRow0 + r1c) * K + k0 + q0 * 8);
        asm volatile("cp.async.commit_group;\n" ::: "memory");
    };

    load_stage(0, 0);

    for (int it = 0; it < nIter; ++it) {
        const int cur = it & 1;
        if (it + 1 < nIter) {
            load_stage(cur ^ 1, (it + 1) * 32);
            asm volatile("cp.async.wait_group 1;\n" ::: "memory");
        } else {
            asm volatile("cp.async.wait_group 0;\n" ::: "memory");
        }
        __syncthreads();

        uint32_t* Ah = smu + cur * STAGE_U;
        uint32_t* Al = Ah + TILE_U;
        uint32_t* Bh = Al + TILE_U;

#pragma unroll
        for (int ks = 0; ks < 2; ++ks) {
            uint32_t ah[2][4], al[2][4];
#pragma unroll
            for (int mt = 0; mt < 2; mt++) {
                int r0 = (wm + mt * 16 + g) * PSTR + ks * 8 + tg;
                int r8 = r0 + 8 * PSTR;
                ah[mt][0] = Ah[r0];     ah[mt][1] = Ah[r8];
                ah[mt][2] = Ah[r0 + 4]; ah[mt][3] = Ah[r8 + 4];
                al[mt][0] = Al[r0];     al[mt][1] = Al[r8];
                al[mt][2] = Al[r0 + 4]; al[mt][3] = Al[r8 + 4];
            }
#pragma unroll
            for (int nt = 0; nt < 8; nt++) {
                int nb = (wn + nt * 8 + g) * PSTR + ks * 8 + tg;
                uint32_t bh0 = Bh[nb], bh1 = Bh[nb + 4];
#pragma unroll
                for (int mt = 0; mt < 2; mt++) {
                    mma_f16(acc[mt][nt], ah[mt], bh0, bh1);
                    mma_f16(acc[mt][nt], al[mt], bh0, bh1);
                }
            }
        }
        __syncthreads();
    }

#pragma unroll
    for (int mt = 0; mt < 2; mt++) {
        int row = blockIdx.y * 128 + wm + mt * 16 + g;
#pragma unroll
        for (int nt = 0; nt < 8; nt++) {
            int col = blockIdx.x * 128 + wn + nt * 8 + tg * 2;
            *(float2*)(C + (size_t)row * N + col)       = make_float2(acc[mt][nt][0], acc[mt][nt][1]);
            *(float2*)(C + (size_t)(row + 8) * N + col) = make_float2(acc[mt][nt][2], acc[mt][nt][3]);
        }
    }
}

// ---------------------------------------------------------------------------
// RoPE (unchanged)
// ---------------------------------------------------------------------------
__global__ void rope_kernel(float* __restrict__ x, int heads)
{
    int idx = blockIdx.x * blockDim.x + threadIdx.x;
    int total = TT * heads * 64;
    if (idx >= total) return;
    int j  = idx & 63;
    int th = idx >> 6;
    int h  = th % heads;
    int t  = th / heads;
    int pos = HIST + (t & (QLEN - 1));

    float e = (float)(2 * j) * (1.0f / 128.0f);
    float freq = powf(1.0e6f, -e);
    float ang = (float)pos * freq;
    float s, c;
    sincosf(ang, &s, &c);

    size_t base = (size_t)t * heads * HD + (size_t)h * HD + j;
    float x0 = x[base];
    float x1 = x[base + 64];
    x[base]      = x0 * c - x1 * s;
    x[base + 64] = x1 * c + x0 * s;
}

// ---------------------------------------------------------------------------
// Tensor-core flash attention (R13 passing version, unchanged — 3-term)
// ---------------------------------------------------------------------------
#define U_QH 0
#define U_QL 4352
#define U_KH 8704
#define U_KL 13056
#define U_VH 17408
#define U_VL 22016
#define U_PH 26624
#define U_PL 28928
#define U_SS 31232
#define U_SA 35392
#define ATT_SMEM_U32 35456
#define ATT_SMEM_BYTES (ATT_SMEM_U32 * 4)

__global__ __launch_bounds__(256) void attn_tc_kernel(
    const float* __restrict__ kcache, const float* __restrict__ vcache)
{
    const int i0  = blockIdx.x * 64;
    const int h   = blockIdx.y;
    const int b   = blockIdx.z;
    const int kvh = h >> 2;
    const int tid = threadIdx.x;
    const int lane = tid & 31;
    const int wid  = tid >> 5;
    const int g    = lane >> 2;
    const int tg   = lane & 3;

    extern __shared__ uint32_t smu[];
    uint32_t* Qh = smu + U_QH;
    uint32_t* Ql = smu + U_QL;
    uint32_t* Kh = smu + U_KH;
    uint32_t* Kl = smu + U_KL;
    uint32_t* Vh = smu + U_VH;
    uint32_t* Vl = smu + U_VL;
    uint32_t* Ph = smu + U_PH;
    uint32_t* Pl = smu + U_PL;
    float*    sS = (float*)(smu + U_SS);
    float*    sA = (float*)(smu + U_SA);

#pragma unroll
    for (int it = 0; it < 8; ++it) {
        int idx = it * 256 + tid;
        int q  = idx >> 5;
        int d4 = (idx & 31) * 4;
        float4 v = *(const float4*)&g_q[(size_t)(b * QLEN + i0 + q) * HH + h * HD + d4];
        v.x *= SCALE; v.y *= SCALE; v.z *= SCALE; v.w *= SCALE;
        uint32_t h0, l0, h1, l1;
        split2(v.x, v.y, h0, l0);
        split2(v.z, v.w, h1, l1);
        int o = q * 68 + (d4 >> 1);
        Qh[o] = h0; Qh[o + 1] = h1;
        Ql[o] = l0; Ql[o + 1] = l1;
    }

    const int wmQ = (wid & 3) * 16;
    const int wnK = (wid >> 2) * 32;
    const int wnD = (wid >> 2) * 64;

    const int srow = tid >> 2, l4 = tid & 3;
    const int vjp = (wid << 2) + (lane >> 3);
    const int vd0 = lane & 7;
    const int pq = tid >> 2, pjb = (tid & 3) * 8;

    float m = NEGBIG, l = 0.f;
    float Oacc[8][4];
#pragma unroll
    for (int nt = 0; nt < 8; nt++)
#pragma unroll
        for (int i = 0; i < 4; i++) Oacc[nt][i] = 0.f;

    for (int t = 0; t < 17; ++t) {
        const int p0 = i0 + t * 64;
        __syncthreads();

#pragma unroll
        for (int it = 0; it < 8; ++it) {
            int idx = it * 256 + tid;
            int r  = idx >> 5;
            int d4 = (idx & 31) * 4;
            int p  = p0 + r;
            const float* src = (p < HIST)
                ? kcache + ((size_t)(b * KVLEN + p) * NKV + kvh) * HD + d4
                : g_k + (size_t)(b * QLEN + (p - HIST)) * DKV + kvh * HD + d4;
            float4 v = *(const float4*)src;
            uint32_t h0, l0, h1, l1;
            split2(v.x, v.y, h0, l0);
            split2(v.z, v.w, h1, l1);
            int o = r * 68 + (d4 >> 1);
            Kh[o] = h0; Kh[o + 1] = h1;
            Kl[o] = l0; Kl[o + 1] = l1;
        }
        {
            int pj0 = p0 + 2 * vjp, pj1 = pj0 + 1;
            const float* s0 = (pj0 < HIST)
                ? vcache + ((size_t)(b * KVLEN + pj0) * NKV + kvh) * HD
                : g_v + (size_t)(b * QLEN + (pj0 - HIST)) * DKV + kvh * HD;
            const float* s1 = (pj1 < HIST)
                ? vcache + ((size_t)(b * KVLEN + pj1) * NKV + kvh) * HD
                : g_v + (size_t)(b * QLEN + (pj1 - HIST)) * DKV + kvh * HD;
#pragma unroll
            for (int i = 0; i < 16; ++i) {
                int d = vd0 + 8 * i;
                uint32_t hh, ll;
                split2(s0[d], s1[d], hh, ll);
                Vh[d * 36 + vjp] = hh;
                Vl[d * 36 + vjp] = ll;
            }
        }
        __syncthreads();

        float Sacc[4][4];
#pragma unroll
        for (int nt = 0; nt < 4; nt++)
#pragma unroll
            for (int i = 0; i < 4; i++) Sacc[nt][i] = 0.f;

#pragma unroll
        for (int ks = 0; ks < 8; ++ks) {
            int r0 = (wmQ + g) * 68 + ks * 8 + tg;
            int r8 = r0 + 8 * 68;
            uint32_t ah[4] = { Qh[r0], Qh[r8], Qh[r0 + 4], Qh[r8 + 4] };
            uint32_t al[4] = { Ql[r0], Ql[r8], Ql[r0 + 4], Ql[r8 + 4] };
#pragma unroll
            for (int nt = 0; nt < 4; nt++) {
                int nb = (wnK + nt * 8 + g) * 68 + ks * 8 + tg;
                uint32_t bh0 = Kh[nb], bh1 = Kh[nb + 4];
                uint32_t bl0 = Kl[nb], bl1 = Kl[nb + 4];
                mma_f16(Sacc[nt], ah, bh0, bh1);
                mma_f16(Sacc[nt], ah, bl0, bl1);
                mma_f16(Sacc[nt], al, bh0, bh1);
            }
        }

        {
            int qi0 = wmQ + g, qi1 = qi0 + 8;
#pragma unroll
            for (int nt = 0; nt < 4; nt++) {
                int ki = wnK + nt * 8 + tg * 2;
                float c0 = Sacc[nt][0], c1 = Sacc[nt][1];
                float c2 = Sacc[nt][2], c3 = Sacc[nt][3];
                if (t == 0) {
                    if (!(ki     > qi0)) c0 = NEGBIG;
                    if (!(ki + 1 > qi0)) c1 = NEGBIG;
                    if (!(ki     > qi1)) c2 = NEGBIG;
                    if (!(ki + 1 > qi1)) c3 = NEGBIG;
                } else if (t == 16) {
                    if (!(ki     <= qi0)) c0 = NEGBIG;
                    if (!(ki + 1 <= qi0)) c1 = NEGBIG;
                    if (!(ki     <= qi1)) c2 = NEGBIG;
                    if (!(ki + 1 <= qi1)) c3 = NEGBIG;
                }
                sS[qi0 * 65 + ki] = c0; sS[qi0 * 65 + ki + 1] = c1;
                sS[qi1 * 65 + ki] = c2; sS[qi1 * 65 + ki + 1] = c3;
            }
        }
        __syncthreads();

        float tm = NEGBIG;
#pragma unroll
        for (int j = 0; j < 16; j++) tm = fmaxf(tm, sS[srow * 65 + l4 * 16 + j]);
        tm = fmaxf(tm, __shfl_xor_sync(0xffffffffu, tm, 1));
        tm = fmaxf(tm, __shfl_xor_sync(0xffffffffu, tm, 2));
        float mnew = fmaxf(m, tm);
        float alpha = __expf(m - mnew);
        float psum = 0.f;
#pragma unroll
        for (int j = 0; j < 16; j++) {
            float p = __expf(sS[srow * 65 + l4 * 16 + j] - mnew);
            sS[srow * 65 + l4 * 16 + j] = p;
            psum += p;
        }
        psum += __shfl_xor_sync(0xffffffffu, psum, 1);
        psum += __shfl_xor_sync(0xffffffffu, psum, 2);
        l = l * alpha + psum;
        m = mnew;
        if (l4 == 0) sA[srow] = alpha;
        __syncthreads();

        {
            float a0 = sA[wmQ + g], a1 = sA[wmQ + g + 8];
#pragma unroll
            for (int nt = 0; nt < 8; nt++) {
                Oacc[nt][0] *= a0; Oacc[nt][1] *= a0;
                Oacc[nt][2] *= a1; Oacc[nt][3] *= a1;
            }
        }
#pragma unroll
        for (int i = 0; i < 8; ++i) {
            int jp = pjb + i;
            uint32_t hh, ll;
            split2(sS[pq * 65 + 2 * jp], sS[pq * 65 + 2 * jp + 1], hh, ll);
            Ph[pq * 36 + jp] = hh;
            Pl[pq * 36 + jp] = ll;
        }
        __syncthreads();

#pragma unroll
        for (int ks = 0; ks < 4; ++ks) {
            int r0 = (wmQ + g) * 36 + ks * 8 + tg;
            int r8 = r0 + 8 * 36;
            uint32_t ph[4] = { Ph[r0], Ph[r8], Ph[r0 + 4], Ph[r8 + 4] };
            uint32_t pl[4] = { Pl[r0], Pl[r8], Pl[r0 + 4], Pl[r8 + 4] };
#pragma unroll
            for (int nt = 0; nt < 8; nt++) {
                int nb = (wnD + nt * 8 + g) * 36 + ks * 8 + tg;
                uint32_t vh0 = Vh[nb], vh1 = Vh[nb + 4];
                uint32_t vl0 = Vl[nb], vl1 = Vl[nb + 4];
                mma_f16(Oacc[nt], ph, vh0, vh1);
                mma_f16(Oacc[nt], ph, vl0, vl1);
                mma_f16(Oacc[nt], pl, vh0, vh1);
            }
        }
    }

    __syncthreads();
    if (l4 == 0) sA[srow] = 1.0f / l;
    __syncthreads();
    {
        float i0v = sA[wmQ + g], i1v = sA[wmQ + g + 8];
        int row0 = b * QLEN + i0 + wmQ + g;
#pragma unroll
        for (int nt = 0; nt < 8; nt++) {
            int col = h * HD + wnD + nt * 8 + tg * 2;
            *(float2*)&g_o[(size_t)row0 * HH + col] =
                make_float2(Oacc[nt][0] * i0v, Oacc[nt][1] * i0v);
            *(float2*)&g_o[(size_t)(row0 + 8) * HH + col] =
                make_float2(Oacc[nt][2] * i1v, Oacc[nt][3] * i1v);
        }
    }
}

// ---------------------------------------------------------------------------
// Launch
// ---------------------------------------------------------------------------
extern "C" void kernel_launch(void* const* d_in, const int* in_sizes, int n_in,
                              void* d_out, int out_size)
{
    const float* hs = (const float*)d_in[0];
    const float* wq = (const float*)d_in[1];
    const float* wk = (const float*)d_in[2];
    const float* wv = (const float*)d_in[3];
    const float* wo = (const float*)d_in[4];
    const float* kc = (const float*)d_in[5];
    const float* vc = (const float*)d_in[6];

    float *qb, *kb, *vb, *ob;
    cudaGetSymbolAddress((void**)&qb, g_q);
    cudaGetSymbolAddress((void**)&kb, g_k);
    cudaGetSymbolAddress((void**)&vb, g_v);
    cudaGetSymbolAddress((void**)&ob, g_o);
    __half *cah, *cal, *wqh, *wkh, *wvh, *woh;
    cudaGetSymbolAddress((void**)&cah, c_ah);
    cudaGetSymbolAddress((void**)&cal, c_al);
    cudaGetSymbolAddress((void**)&wqh, w_qh);
    cudaGetSymbolAddress((void**)&wkh, w_kh);
    cudaGetSymbolAddress((void**)&wvh, w_vh);
    cudaGetSymbolAddress((void**)&woh, w_oh);

    cudaFuncSetAttribute(hgemm2_kernel, cudaFuncAttributeMaxDynamicSharedMemorySize,
                         PG_SMEM_BYTES);
    cudaFuncSetAttribute(attn_tc_kernel, cudaFuncAttributeMaxDynamicSharedMemorySize,
                         ATT_SMEM_BYTES);

    const int n4hh = TT * HH / 4;

    conv_a_kernel<<<(n4hh + 255) / 256, 256>>>(hs, cah, cal, n4hh);
    conv_b_kernel<<<dim3(HH / 32, HH / 32),  256>>>(wq, wqh, HH, HH);
    conv_b_kernel<<<dim3(DKV / 32, HH / 32), 256>>>(wk, wkh, HH, DKV);
    conv_b_kernel<<<dim3(DKV / 32, HH / 32), 256>>>(wv, wvh, HH, DKV);
    conv_b_kernel<<<dim3(HH / 32, HH / 32),  256>>>(wo, woh, HH, HH);

    dim3 gq(HH / 128, TT / 128);
    dim3 gkv(DKV / 128, TT / 128);

    hgemm2_kernel<<<gq,  256, PG_SMEM_BYTES>>>(TT, HH,  HH, cah, cal, wqh, qb);
    hgemm2_kernel<<<gkv, 256, PG_SMEM_BYTES>>>(TT, DKV, HH, cah, cal, wkh, kb);
    hgemm2_kernel<<<gkv, 256, PG_SMEM_BYTES>>>(TT, DKV, HH, cah, cal, wvh, vb);

    {
        int totq = TT * NHEADS * 64;
        rope_kernel<<<(totq + 255) / 256, 256>>>(qb, NHEADS);
        int totk = TT * NKV * 64;
        rope_kernel<<<(totk + 255) / 256, 256>>>(kb, NKV);
    }

    dim3 ga(QLEN / 64, NHEADS, BATCH);
    attn_tc_kernel<<<ga, 256, ATT_SMEM_BYTES>>>(kc, vc);

    conv_a_kernel<<<(n4hh + 255) / 256, 256>>>(ob, cah, cal, n4hh);
    hgemm2_kernel<<<gq, 256, PG_SMEM_BYTES>>>(TT, HH, HH, cah, cal, woh, (float*)d_out);
}